// round 11
// baseline (speedup 1.0000x reference)
#include <cuda_runtime.h>
#include <cuda_fp16.h>
#include <cstdint>

#define BB   2
#define CFI  32
#define HH   192
#define WWD  192
#define NN   (HH*WWD)        // 36864
#define NUMK 16
#define CT   67
#define EPSL 1e-5f
#define TS   256
#define NT   (NN/TS)         // 144

// ---------------- scratch (static device globals; no allocation) ----------------
__device__ float g_P[BB*NN*CFI];        // [b][n][c]
__device__ float g_Q[BB*NN*CFI];        // [b][n][c]
__device__ float g_U[BB*NUMK*NN];
__device__ float g_Om[BB*NUMK*NN];

__device__ float g_WPQ[64*32];
__device__ float g_w1p[32], g_w1a[32], g_w1b[32], g_t1[32];
// packed f16x2 weights per layer: [k2][32] uint32 (single precision pass)
__device__ unsigned g_W2p[512];
__device__ unsigned g_W3p[512];
__device__ unsigned g_W4p[512];
__device__ float g_t2[32], g_t3[32], g_t4[32];
__device__ float g_wcA[32], g_wcB[32], g_wcC[32];
__device__ float g_bcv[3];
__device__ int   g_args64;

__device__ __forceinline__ float frcp(float x) { float y; asm("rcp.approx.f32 %0, %1;" : "=f"(y) : "f"(x)); return y; }
__device__ __forceinline__ float fex2(float x) { float y; asm("ex2.approx.f32 %0, %1;" : "=f"(y) : "f"(x)); return y; }

// ---------------- packed f32x2 helpers ----------------
__device__ __forceinline__ float2 fma2(float2 a, float2 b, float2 c) {
    float2 r;
    asm("fma.rn.f32x2 %0, %1, %2, %3;"
        : "=l"(*(unsigned long long*)&r)
        : "l"(*(const unsigned long long*)&a),
          "l"(*(const unsigned long long*)&b),
          "l"(*(const unsigned long long*)&c));
    return r;
}
__device__ __forceinline__ float2 mul2(float2 a, float2 b) {
    float2 r;
    asm("mul.rn.f32x2 %0, %1, %2;"
        : "=l"(*(unsigned long long*)&r)
        : "l"(*(const unsigned long long*)&a),
          "l"(*(const unsigned long long*)&b));
    return r;
}
__device__ __forceinline__ float2 add2(float2 a, float2 b) {
    float2 r;
    asm("add.rn.f32x2 %0, %1, %2;"
        : "=l"(*(unsigned long long*)&r)
        : "l"(*(const unsigned long long*)&a),
          "l"(*(const unsigned long long*)&b));
    return r;
}
__device__ __forceinline__ float2 d2(float v) { return make_float2(v, v); }

// packed fast gelu: 0.5*(x + |x|*erf(|x|/sqrt2))
// erf via A&S 7.1.26 rational-power: erf(z) = 1 - (1 + a1 z + ... + a6 z^6)^-16, |eps|<=3e-7
// only ONE MUFU (rcp) per element; w^16 -> inf saturates cleanly (rcp(inf)=0 -> erf=1).
__device__ __forceinline__ float2 gelu2(float2 x) {
    unsigned long long ux = (*(unsigned long long*)&x) & 0x7FFFFFFF7FFFFFFFULL;
    float2 ax = *(float2*)&ux;                         // alu pipe (LOP)
    float2 z  = mul2(ax, d2(0.70710678118654752f));
    float2 w  = fma2(z, d2(0.0000430638f), d2(0.0002765672f));
    w = fma2(w, z, d2(0.0001520143f));
    w = fma2(w, z, d2(0.0092705272f));
    w = fma2(w, z, d2(0.0422820123f));
    w = fma2(w, z, d2(0.0705230784f));
    w = fma2(w, z, d2(1.0f));
    float2 w2  = mul2(w,  w);
    float2 w4  = mul2(w2, w2);
    float2 w8  = mul2(w4, w4);
    float2 w16 = mul2(w8, w8);
    float2 t; t.x = frcp(w16.x); t.y = frcp(w16.y);    // MUFU x2 (one per element)
    float2 E  = fma2(t, d2(-1.0f), d2(1.0f));          // erf(z), z >= 0
    float2 g  = mul2(ax, E);
    return mul2(add2(x, g), d2(0.5f));
}

// m16n8k16 fp16 MMA, row.col, fp32 accumulate in-place
__device__ __forceinline__ void mma16(float* d, unsigned a0, unsigned a1, unsigned a2, unsigned a3,
                                      unsigned b0, unsigned b1) {
    asm volatile(
        "mma.sync.aligned.m16n8k16.row.col.f32.f16.f16.f32 "
        "{%0,%1,%2,%3}, {%4,%5,%6,%7}, {%8,%9}, {%0,%1,%2,%3};"
        : "+f"(d[0]), "+f"(d[1]), "+f"(d[2]), "+f"(d[3])
        : "r"(a0), "r"(a1), "r"(a2), "r"(a3), "r"(b0), "r"(b1));
}

// ---------------- kernel 1: fold BN, pack fp16 weights, detect args dtype ----------------
__global__ void prep_kernel(
    const float* __restrict__ W1, const float* __restrict__ g1, const float* __restrict__ b1,
    const float* __restrict__ m1, const float* __restrict__ v1,
    const float* __restrict__ W2, const float* __restrict__ g2, const float* __restrict__ b2,
    const float* __restrict__ m2, const float* __restrict__ v2,
    const float* __restrict__ W3, const float* __restrict__ g3, const float* __restrict__ b3,
    const float* __restrict__ m3, const float* __restrict__ v3,
    const float* __restrict__ W4, const float* __restrict__ g4, const float* __restrict__ b4,
    const float* __restrict__ m4, const float* __restrict__ v4,
    const float* __restrict__ Wc, const float* __restrict__ bc,
    const int*   __restrict__ args_i32)
{
    __shared__ float inv1[32], inv2[32], inv3[32], inv4[32];
    int t = threadIdx.x;
    if (t < 32) {
        float i1 = g1[t]*rsqrtf(v1[t]+EPSL); inv1[t]=i1; g_t1[t]=b1[t]-m1[t]*i1;
        float i2 = g2[t]*rsqrtf(v2[t]+EPSL); inv2[t]=i2; g_t2[t]=b2[t]-m2[t]*i2;
        float i3 = g3[t]*rsqrtf(v3[t]+EPSL); inv3[t]=i3; g_t3[t]=b3[t]-m3[t]*i3;
        float i4 = g4[t]*rsqrtf(v4[t]+EPSL); inv4[t]=i4; g_t4[t]=b4[t]-m4[t]*i4;
        g_wcA[t]=Wc[t]; g_wcB[t]=Wc[32+t]; g_wcC[t]=Wc[64+t];
        g_w1p[t]=W1[t*CT+64]*i1; g_w1a[t]=W1[t*CT+65]*i1; g_w1b[t]=W1[t*CT+66]*i1;
    }
    if (t < 3) g_bcv[t] = bc[t];
    if (t == 0) {
        int all_zero = 1;
        for (int i = 0; i < 128; i++) if (args_i32[2*i+1] != 0) { all_zero = 0; break; }
        g_args64 = all_zero;
    }
    __syncthreads();
    for (int idx = t; idx < 2048; idx += blockDim.x) {
        int r = idx >> 5, i = idx & 31;
        g_WPQ[idx] = (r < 32) ? W1[r*CT + i] * inv1[r]
                              : W1[(r-32)*CT + 32 + i] * inv1[r-32];
    }
    // packed fp16 weights: idx = k2*32 + n
    for (int idx = t; idx < 512; idx += blockDim.x) {
        int k2 = idx >> 5, n = idx & 31;
        __half2 p;
        p = __floats2half2_rn(W2[n*32 + 2*k2]*inv2[n], W2[n*32 + 2*k2 + 1]*inv2[n]);
        g_W2p[idx] = *(unsigned*)&p;
        p = __floats2half2_rn(W3[n*32 + 2*k2]*inv3[n], W3[n*32 + 2*k2 + 1]*inv3[n]);
        g_W3p[idx] = *(unsigned*)&p;
        p = __floats2half2_rn(W4[n*32 + 2*k2]*inv4[n], W4[n*32 + 2*k2 + 1]*inv4[n]);
        g_W4p[idx] = *(unsigned*)&p;
    }
}

// ---------------- kernel 2: P/Q = folded-W1 @ If, written [b][n][c] ----------------
__global__ void pq_kernel(const float* __restrict__ If)
{
    __shared__ float wf[2048];
    __shared__ float tb[256*33];
    int tid  = threadIdx.x;
    int b    = blockIdx.x / NT;
    int tile = blockIdx.x % NT;
    int n0   = tile * 256;

    for (int idx = tid; idx < 2048; idx += 256) wf[idx] = g_WPQ[idx];

    int n = n0 + tid;
    float x[32];
    #pragma unroll
    for (int i = 0; i < 32; i++) x[i] = If[((size_t)b*32 + i)*NN + n];
    __syncthreads();

    size_t base = ((size_t)b*NN + n0) * 32;

    #pragma unroll
    for (int c = 0; c < 32; c++) {
        float acc = 0.f;
        #pragma unroll
        for (int i = 0; i < 32; i += 4) {
            float4 w = *(const float4*)&wf[c*32 + i];
            acc += w.x*x[i] + w.y*x[i+1] + w.z*x[i+2] + w.w*x[i+3];
        }
        tb[tid*33 + c] = acc;
    }
    __syncthreads();
    for (int idx = tid; idx < 8192; idx += 256)
        g_P[base + idx] = tb[(idx >> 5)*33 + (idx & 31)];
    __syncthreads();

    #pragma unroll
    for (int c = 0; c < 32; c++) {
        float acc = 0.f;
        #pragma unroll
        for (int i = 0; i < 32; i += 4) {
            float4 w = *(const float4*)&wf[(32+c)*32 + i];
            acc += w.x*x[i] + w.y*x[i+1] + w.z*x[i+2] + w.w*x[i+3];
        }
        tb[tid*33 + c] = acc;
    }
    __syncthreads();
    for (int idx = tid; idx < 8192; idx += 256)
        g_Q[base + idx] = tb[(idx >> 5)*33 + (idx & 31)];
}

// ---------------- register-resident MLP layer (single-pass fp16 mma) ----------------
// x layout: x[mt*16 + nt*4 + e], channel = 8*nt + 2*tg + (e&1),
//           sample row = 32*warp + 16*mt + g + 8*(e>>1)
template<bool ADD>
__device__ __forceinline__ void layer_reg(
    const float* xin, float* xout,
    const unsigned* __restrict__ wp, const float* __restrict__ bias,
    const float* resid, int g, int tg)
{
    // pack activations to fp16
    unsigned ah[16];
    #pragma unroll
    for (int mt = 0; mt < 2; mt++)
    #pragma unroll
    for (int nt = 0; nt < 4; nt++) {
        int base = mt*16 + nt*4;
        #pragma unroll
        for (int hh = 0; hh < 2; hh++) {
            __half2 p = __floats2half2_rn(xin[base + 2*hh], xin[base + 2*hh + 1]);
            ah[(mt*4 + nt)*2 + hh] = *(unsigned*)&p;
        }
    }
    // init accumulators with bias
    float d[32];
    #pragma unroll
    for (int nt = 0; nt < 4; nt++) {
        float2 bv = __ldg((const float2*)bias + 4*nt + tg);
        #pragma unroll
        for (int mt = 0; mt < 2; mt++) {
            d[mt*16 + nt*4 + 0] = bv.x; d[mt*16 + nt*4 + 1] = bv.y;
            d[mt*16 + nt*4 + 2] = bv.x; d[mt*16 + nt*4 + 3] = bv.y;
        }
    }
    // mma mainloop: 2 k-steps x 4 n-tiles x 2 m-tiles, single pass
    #pragma unroll
    for (int ks = 0; ks < 2; ks++) {
        #pragma unroll
        for (int nt = 0; nt < 4; nt++) {
            unsigned b0 = __ldg(wp + (ks*8 + tg    )*32 + 8*nt + g);
            unsigned b1 = __ldg(wp + (ks*8 + tg + 4)*32 + 8*nt + g);
            #pragma unroll
            for (int mt = 0; mt < 2; mt++) {
                int ia  = (mt*4 + 2*ks    )*2;
                int ia2 = (mt*4 + 2*ks + 1)*2;
                mma16(d + mt*16 + nt*4, ah[ia], ah[ia+1], ah[ia2], ah[ia2+1], b0, b1);
            }
        }
    }
    // packed-pair gelu epilogue (pairs = adjacent channels, natural D-frag pairs)
    #pragma unroll
    for (int i = 0; i < 32; i += 2) {
        float2 v = make_float2(d[i], d[i+1]);
        if (ADD) v = add2(v, make_float2(resid[i], resid[i+1]));
        float2 r = gelu2(v);
        xout[i] = r.x; xout[i+1] = r.y;
    }
}

// ---------------- kernel 3: main fused MLP, fully register-resident ----------------
__global__ void __launch_bounds__(256) main_kernel(
    const float* __restrict__ Pf,
    const float* __restrict__ Of,
    const void*  __restrict__ args)
{
    int bk   = blockIdx.x / NT;
    int tile = blockIdx.x % NT;
    int b = bk / NUMK, k = bk % NUMK;
    int n0 = tile * TS;
    int tid = threadIdx.x;
    int w = tid >> 5, lane = tid & 31;
    int g = lane >> 2, tg = lane & 3;

    float xa[32], xb[32];
    float pfs[4];

    // stage 1: h1 in D-frag register layout (packed f32x2 arithmetic)
    {
        float2 w1p2[4], w1a2[4], w1b2[4], t12[4];
        #pragma unroll
        for (int q = 0; q < 4; q++) {
            w1p2[q] = __ldg((const float2*)g_w1p + 4*q + tg);
            w1a2[q] = __ldg((const float2*)g_w1a + 4*q + tg);
            w1b2[q] = __ldg((const float2*)g_w1b + 4*q + tg);
            t12[q]  = __ldg((const float2*)g_t1  + 4*q + tg);
        }
        const float* of0p = Of + ((size_t)(b*2+0)*NUMK + k)*NN;
        const float* of1p = Of + ((size_t)(b*2+1)*NUMK + k)*NN;
        int use64 = g_args64;
        #pragma unroll
        for (int mt = 0; mt < 2; mt++)
        #pragma unroll
        for (int hh = 0; hh < 2; hh++) {
            int s = 32*w + 16*mt + 8*hh + g;
            int n = n0 + s;
            size_t ai = ((size_t)(b*NUMK + k))*NN + n;
            int j;
            if (use64) j = (int)__ldg((const long long*)args + ai);
            else       j = __ldg((const int*)args + ai);
            float pf = __ldg(Pf + (size_t)b*NN + j);
            pfs[mt*2 + hh] = pf;
            float2 pf2 = d2(pf);
            float2 o02 = d2(__ldg(of0p + n));
            float2 o12 = d2(__ldg(of1p + n));
            const float2* P2 = (const float2*)g_P + (size_t)(b*NN + n)*16 + tg;
            const float2* Q2 = (const float2*)g_Q + (size_t)(b*NN + j)*16 + tg;
            #pragma unroll
            for (int q = 0; q < 4; q++) {
                float2 p  = __ldg(P2 + 4*q);
                float2 qv = __ldg(Q2 + 4*q);
                float2 z = add2(add2(p, qv), t12[q]);
                z = fma2(w1p2[q], pf2, z);
                z = fma2(w1a2[q], o02, z);
                z = fma2(w1b2[q], o12, z);
                float2 r = gelu2(z);
                xa[mt*16 + q*4 + 2*hh]     = r.x;
                xa[mt*16 + q*4 + 2*hh + 1] = r.y;
            }
        }
    }

    layer_reg<false>(xa, xb, g_W2p, g_t2, nullptr, g, tg);   // h2 = xb
    layer_reg<false>(xb, xa, g_W3p, g_t3, nullptr, g, tg);   // l3 = xa
    layer_reg<true >(xa, xa, g_W4p, g_t4, xb,      g, tg);   // XF = gelu(h2 + bn4(W4 l3))

    // head: 3x32 dot per sample in packed pairs, reduce across tg-lanes
    {
        float2 wA2[4], wB2[4], wC2[4];
        #pragma unroll
        for (int nt = 0; nt < 4; nt++) {
            wA2[nt] = __ldg((const float2*)g_wcA + 4*nt + tg);
            wB2[nt] = __ldg((const float2*)g_wcB + 4*nt + tg);
            wC2[nt] = __ldg((const float2*)g_wcC + 4*nt + tg);
        }
        float bc0 = g_bcv[0], bc1 = g_bcv[1], bc2 = g_bcv[2];
        size_t obase = ((size_t)(b*NUMK + k))*NN + n0;
        #pragma unroll
        for (int mt = 0; mt < 2; mt++)
        #pragma unroll
        for (int hh = 0; hh < 2; hh++) {
            float2 a2 = d2(0.f), be2 = d2(0.f), om2 = d2(0.f);
            #pragma unroll
            for (int nt = 0; nt < 4; nt++) {
                float2 xp = make_float2(xa[mt*16 + nt*4 + 2*hh], xa[mt*16 + nt*4 + 2*hh + 1]);
                a2  = fma2(wA2[nt], xp, a2);
                be2 = fma2(wB2[nt], xp, be2);
                om2 = fma2(wC2[nt], xp, om2);
            }
            float a = a2.x + a2.y, be = be2.x + be2.y, om = om2.x + om2.y;
            a  += __shfl_xor_sync(0xffffffffu, a, 1);
            a  += __shfl_xor_sync(0xffffffffu, a, 2);
            be += __shfl_xor_sync(0xffffffffu, be, 1);
            be += __shfl_xor_sync(0xffffffffu, be, 2);
            om += __shfl_xor_sync(0xffffffffu, om, 1);
            om += __shfl_xor_sync(0xffffffffu, om, 2);
            if (tg == 0) {
                int s = 32*w + 16*mt + 8*hh + g;
                float U = (a + bc0 + 1.0f)*pfs[mt*2 + hh] + (be + bc1);
                g_U[obase + s]  = U;
                g_Om[obase + s] = om + bc2;
            }
        }
    }
}

// ---------------- kernel 4: softmax over NUM + weighted sum ----------------
__global__ void epi_kernel(float* __restrict__ out)
{
    int gid = blockIdx.x * blockDim.x + threadIdx.x;
    if (gid >= BB*NN) return;
    int b = gid / NN, n = gid % NN;
    size_t base = (size_t)b*NUMK*NN + n;
    float om[NUMK];
    float m = -3.4e38f;
    #pragma unroll
    for (int k = 0; k < NUMK; k++) {
        om[k] = g_Om[base + (size_t)k*NN];
        m = fmaxf(m, om[k]);
    }
    float num = 0.f, den = 0.f;
    #pragma unroll
    for (int k = 0; k < NUMK; k++) {
        float e = fex2((om[k] - m) * 1.4426950408889634f);
        den += e;
        num += e * g_U[base + (size_t)k*NN];
    }
    out[gid] = num * frcp(den);
}

// ---------------- launch ----------------
extern "C" void kernel_launch(void* const* d_in, const int* in_sizes, int n_in,
                              void* d_out, int out_size)
{
    const float* If = (const float*)d_in[0];
    const float* Pf = (const float*)d_in[1];
    const float* Of = (const float*)d_in[2];
    const void*  args = d_in[3];
    const float* W1 = (const float*)d_in[4];
    const float* g1 = (const float*)d_in[5];
    const float* b1 = (const float*)d_in[6];
    const float* m1 = (const float*)d_in[7];
    const float* v1 = (const float*)d_in[8];
    const float* W2 = (const float*)d_in[9];
    const float* g2 = (const float*)d_in[10];
    const float* b2 = (const float*)d_in[11];
    const float* m2 = (const float*)d_in[12];
    const float* v2 = (const float*)d_in[13];
    const float* W3 = (const float*)d_in[14];
    const float* g3 = (const float*)d_in[15];
    const float* b3 = (const float*)d_in[16];
    const float* m3 = (const float*)d_in[17];
    const float* v3 = (const float*)d_in[18];
    const float* W4 = (const float*)d_in[19];
    const float* g4 = (const float*)d_in[20];
    const float* b4 = (const float*)d_in[21];
    const float* m4 = (const float*)d_in[22];
    const float* v4 = (const float*)d_in[23];
    const float* Wc = (const float*)d_in[24];
    const float* bc = (const float*)d_in[25];

    prep_kernel<<<1, 256>>>(W1, g1, b1, m1, v1,
                            W2, g2, b2, m2, v2,
                            W3, g3, b3, m3, v3,
                            W4, g4, b4, m4, v4,
                            Wc, bc, (const int*)args);

    pq_kernel<<<BB*NT, 256>>>(If);

    main_kernel<<<BB*NUMK*NT, 256>>>(Pf, Of, args);

    epi_kernel<<<(BB*NN + 255)/256, 256>>>((float*)d_out);
}

// round 12
// speedup vs baseline: 1.0130x; 1.0130x over previous
#include <cuda_runtime.h>
#include <cuda_fp16.h>
#include <cstdint>

#define BB   2
#define CFI  32
#define HH   192
#define WWD  192
#define NN   (HH*WWD)        // 36864
#define NUMK 16
#define CT   67
#define EPSL 1e-5f
#define TS   256
#define NT   (NN/TS)         // 144

// ---------------- scratch (static device globals; no allocation) ----------------
// g_P/g_Q rows are PERMUTED: within a row, channel c sits at
// p = ((c>>1)&3)*8 + ((c>>3)<<1) + (c&1)  (thread tg owns bytes [tg*32, tg*32+32))
__device__ float g_P[BB*NN*CFI];
__device__ float g_Q[BB*NN*CFI];
__device__ float g_U[BB*NUMK*NN];
__device__ float g_Om[BB*NUMK*NN];

__device__ float g_WPQ[64*32];
__device__ float g_w1p[32], g_w1a[32], g_w1b[32], g_t1[32];
// packed f16x2 weights per layer: [k2][32] uint32 (single precision pass)
__device__ unsigned g_W2p[512];
__device__ unsigned g_W3p[512];
__device__ unsigned g_W4p[512];
__device__ float g_t2[32], g_t3[32], g_t4[32];
__device__ float g_wcA[32], g_wcB[32], g_wcC[32];
__device__ float g_bcv[3];
__device__ int   g_args64;

__device__ __forceinline__ float frcp(float x) { float y; asm("rcp.approx.f32 %0, %1;" : "=f"(y) : "f"(x)); return y; }
__device__ __forceinline__ float fex2(float x) { float y; asm("ex2.approx.f32 %0, %1;" : "=f"(y) : "f"(x)); return y; }

// ---------------- packed f32x2 helpers ----------------
__device__ __forceinline__ float2 fma2(float2 a, float2 b, float2 c) {
    float2 r;
    asm("fma.rn.f32x2 %0, %1, %2, %3;"
        : "=l"(*(unsigned long long*)&r)
        : "l"(*(const unsigned long long*)&a),
          "l"(*(const unsigned long long*)&b),
          "l"(*(const unsigned long long*)&c));
    return r;
}
__device__ __forceinline__ float2 mul2(float2 a, float2 b) {
    float2 r;
    asm("mul.rn.f32x2 %0, %1, %2;"
        : "=l"(*(unsigned long long*)&r)
        : "l"(*(const unsigned long long*)&a),
          "l"(*(const unsigned long long*)&b));
    return r;
}
__device__ __forceinline__ float2 add2(float2 a, float2 b) {
    float2 r;
    asm("add.rn.f32x2 %0, %1, %2;"
        : "=l"(*(unsigned long long*)&r)
        : "l"(*(const unsigned long long*)&a),
          "l"(*(const unsigned long long*)&b));
    return r;
}
__device__ __forceinline__ float2 d2(float v) { return make_float2(v, v); }

// packed fast gelu (R10 version): 0.5*(x + |x|*erf(|x|/sqrt2)),
// erf via A&S 7.1.25 3-term (|eps|<=2.5e-5); 2 MUFU, ~11 fma-class per pair
__device__ __forceinline__ float2 gelu2(float2 x) {
    unsigned long long ux = (*(unsigned long long*)&x) & 0x7FFFFFFF7FFFFFFFULL;
    float2 ax = *(float2*)&ux;                         // alu pipe (LOP)
    float2 z  = mul2(ax, d2(0.70710678118654752f));
    float2 q  = fma2(z, d2(0.47047f), d2(1.0f));
    float2 t; t.x = frcp(q.x); t.y = frcp(q.y);        // MUFU
    float2 s  = mul2(mul2(z, z), d2(-1.4426950408889634f));
    float2 e; e.x = fex2(s.x); e.y = fex2(s.y);        // MUFU
    float2 h  = fma2(d2(0.7478556f), t, d2(-0.0958798f));
    h = fma2(h, t, d2(0.3480242f));
    h = mul2(h, t);
    float2 he = mul2(h, e);
    float2 E  = fma2(he, d2(-1.0f), d2(1.0f));         // erf(z), z >= 0
    float2 g  = mul2(ax, E);
    return mul2(add2(x, g), d2(0.5f));
}

// m16n8k16 fp16 MMA, row.col, fp32 accumulate in-place
__device__ __forceinline__ void mma16(float* d, unsigned a0, unsigned a1, unsigned a2, unsigned a3,
                                      unsigned b0, unsigned b1) {
    asm volatile(
        "mma.sync.aligned.m16n8k16.row.col.f32.f16.f16.f32 "
        "{%0,%1,%2,%3}, {%4,%5,%6,%7}, {%8,%9}, {%0,%1,%2,%3};"
        : "+f"(d[0]), "+f"(d[1]), "+f"(d[2]), "+f"(d[3])
        : "r"(a0), "r"(a1), "r"(a2), "r"(a3), "r"(b0), "r"(b1));
}

// ---------------- kernel 1: fold BN, pack fp16 weights, detect args dtype ----------------
__global__ void prep_kernel(
    const float* __restrict__ W1, const float* __restrict__ g1, const float* __restrict__ b1,
    const float* __restrict__ m1, const float* __restrict__ v1,
    const float* __restrict__ W2, const float* __restrict__ g2, const float* __restrict__ b2,
    const float* __restrict__ m2, const float* __restrict__ v2,
    const float* __restrict__ W3, const float* __restrict__ g3, const float* __restrict__ b3,
    const float* __restrict__ m3, const float* __restrict__ v3,
    const float* __restrict__ W4, const float* __restrict__ g4, const float* __restrict__ b4,
    const float* __restrict__ m4, const float* __restrict__ v4,
    const float* __restrict__ Wc, const float* __restrict__ bc,
    const int*   __restrict__ args_i32)
{
    __shared__ float inv1[32], inv2[32], inv3[32], inv4[32];
    int t = threadIdx.x;
    if (t < 32) {
        float i1 = g1[t]*rsqrtf(v1[t]+EPSL); inv1[t]=i1; g_t1[t]=b1[t]-m1[t]*i1;
        float i2 = g2[t]*rsqrtf(v2[t]+EPSL); inv2[t]=i2; g_t2[t]=b2[t]-m2[t]*i2;
        float i3 = g3[t]*rsqrtf(v3[t]+EPSL); inv3[t]=i3; g_t3[t]=b3[t]-m3[t]*i3;
        float i4 = g4[t]*rsqrtf(v4[t]+EPSL); inv4[t]=i4; g_t4[t]=b4[t]-m4[t]*i4;
        g_wcA[t]=Wc[t]; g_wcB[t]=Wc[32+t]; g_wcC[t]=Wc[64+t];
        g_w1p[t]=W1[t*CT+64]*i1; g_w1a[t]=W1[t*CT+65]*i1; g_w1b[t]=W1[t*CT+66]*i1;
    }
    if (t < 3) g_bcv[t] = bc[t];
    if (t == 0) {
        int all_zero = 1;
        for (int i = 0; i < 128; i++) if (args_i32[2*i+1] != 0) { all_zero = 0; break; }
        g_args64 = all_zero;
    }
    __syncthreads();
    for (int idx = t; idx < 2048; idx += blockDim.x) {
        int r = idx >> 5, i = idx & 31;
        g_WPQ[idx] = (r < 32) ? W1[r*CT + i] * inv1[r]
                              : W1[(r-32)*CT + 32 + i] * inv1[r-32];
    }
    // packed fp16 weights: idx = k2*32 + n
    for (int idx = t; idx < 512; idx += blockDim.x) {
        int k2 = idx >> 5, n = idx & 31;
        __half2 p;
        p = __floats2half2_rn(W2[n*32 + 2*k2]*inv2[n], W2[n*32 + 2*k2 + 1]*inv2[n]);
        g_W2p[idx] = *(unsigned*)&p;
        p = __floats2half2_rn(W3[n*32 + 2*k2]*inv3[n], W3[n*32 + 2*k2 + 1]*inv3[n]);
        g_W3p[idx] = *(unsigned*)&p;
        p = __floats2half2_rn(W4[n*32 + 2*k2]*inv4[n], W4[n*32 + 2*k2 + 1]*inv4[n]);
        g_W4p[idx] = *(unsigned*)&p;
    }
}

// channel -> permuted position within a 32-float P/Q row
__device__ __forceinline__ int permc(int c) {
    return ((c >> 1) & 3) * 8 + ((c >> 3) << 1) + (c & 1);
}

// ---------------- kernel 2: P/Q = folded-W1 @ If, permuted [b][n][p] ----------------
__global__ void pq_kernel(const float* __restrict__ If)
{
    __shared__ float wf[2048];
    __shared__ float tb[256*33];
    int tid  = threadIdx.x;
    int b    = blockIdx.x / NT;
    int tile = blockIdx.x % NT;
    int n0   = tile * 256;

    for (int idx = tid; idx < 2048; idx += 256) wf[idx] = g_WPQ[idx];

    int n = n0 + tid;
    float x[32];
    #pragma unroll
    for (int i = 0; i < 32; i++) x[i] = If[((size_t)b*32 + i)*NN + n];
    __syncthreads();

    size_t base = ((size_t)b*NN + n0) * 32;

    #pragma unroll
    for (int c = 0; c < 32; c++) {
        float acc = 0.f;
        #pragma unroll
        for (int i = 0; i < 32; i += 4) {
            float4 w = *(const float4*)&wf[c*32 + i];
            acc += w.x*x[i] + w.y*x[i+1] + w.z*x[i+2] + w.w*x[i+3];
        }
        tb[tid*33 + c] = acc;
    }
    __syncthreads();
    for (int idx = tid; idx < 8192; idx += 256)
        g_P[base + (idx & ~31) + permc(idx & 31)] = tb[(idx >> 5)*33 + (idx & 31)];
    __syncthreads();

    #pragma unroll
    for (int c = 0; c < 32; c++) {
        float acc = 0.f;
        #pragma unroll
        for (int i = 0; i < 32; i += 4) {
            float4 w = *(const float4*)&wf[(32+c)*32 + i];
            acc += w.x*x[i] + w.y*x[i+1] + w.z*x[i+2] + w.w*x[i+3];
        }
        tb[tid*33 + c] = acc;
    }
    __syncthreads();
    for (int idx = tid; idx < 8192; idx += 256)
        g_Q[base + (idx & ~31) + permc(idx & 31)] = tb[(idx >> 5)*33 + (idx & 31)];
}

// ---------------- register-resident MLP layer (single-pass fp16 mma) ----------------
// x layout: x[mt*16 + nt*4 + e], channel = 8*nt + 2*tg + (e&1),
//           sample row = 32*warp + 16*mt + g + 8*(e>>1)
template<bool ADD>
__device__ __forceinline__ void layer_reg(
    const float* xin, float* xout,
    const unsigned* __restrict__ wp, const float* __restrict__ bias,
    const float* resid, int g, int tg)
{
    // pack activations to fp16
    unsigned ah[16];
    #pragma unroll
    for (int mt = 0; mt < 2; mt++)
    #pragma unroll
    for (int nt = 0; nt < 4; nt++) {
        int base = mt*16 + nt*4;
        #pragma unroll
        for (int hh = 0; hh < 2; hh++) {
            __half2 p = __floats2half2_rn(xin[base + 2*hh], xin[base + 2*hh + 1]);
            ah[(mt*4 + nt)*2 + hh] = *(unsigned*)&p;
        }
    }
    // init accumulators with bias
    float d[32];
    #pragma unroll
    for (int nt = 0; nt < 4; nt++) {
        float2 bv = __ldg((const float2*)bias + 4*nt + tg);
        #pragma unroll
        for (int mt = 0; mt < 2; mt++) {
            d[mt*16 + nt*4 + 0] = bv.x; d[mt*16 + nt*4 + 1] = bv.y;
            d[mt*16 + nt*4 + 2] = bv.x; d[mt*16 + nt*4 + 3] = bv.y;
        }
    }
    // mma mainloop: 2 k-steps x 4 n-tiles x 2 m-tiles, single pass
    #pragma unroll
    for (int ks = 0; ks < 2; ks++) {
        #pragma unroll
        for (int nt = 0; nt < 4; nt++) {
            unsigned b0 = __ldg(wp + (ks*8 + tg    )*32 + 8*nt + g);
            unsigned b1 = __ldg(wp + (ks*8 + tg + 4)*32 + 8*nt + g);
            #pragma unroll
            for (int mt = 0; mt < 2; mt++) {
                int ia  = (mt*4 + 2*ks    )*2;
                int ia2 = (mt*4 + 2*ks + 1)*2;
                mma16(d + mt*16 + nt*4, ah[ia], ah[ia+1], ah[ia2], ah[ia2+1], b0, b1);
            }
        }
    }
    // packed-pair gelu epilogue
    #pragma unroll
    for (int i = 0; i < 32; i += 2) {
        float2 v = make_float2(d[i], d[i+1]);
        if (ADD) v = add2(v, make_float2(resid[i], resid[i+1]));
        float2 r = gelu2(v);
        xout[i] = r.x; xout[i+1] = r.y;
    }
}

// ---------------- kernel 3: main fused MLP, fully register-resident ----------------
__global__ void __launch_bounds__(256) main_kernel(
    const float* __restrict__ Pf,
    const float* __restrict__ Of,
    const void*  __restrict__ args)
{
    int bk   = blockIdx.x / NT;
    int tile = blockIdx.x % NT;
    int b = bk / NUMK, k = bk % NUMK;
    int n0 = tile * TS;
    int tid = threadIdx.x;
    int w = tid >> 5, lane = tid & 31;
    int g = lane >> 2, tg = lane & 3;

    float xa[32], xb[32];
    float pfs[4];

    // stage 1: h1 in D-frag register layout (packed math + vectorized P/Q loads)
    {
        float2 w1p2[4], w1a2[4], w1b2[4], t12[4];
        #pragma unroll
        for (int q = 0; q < 4; q++) {
            w1p2[q] = __ldg((const float2*)g_w1p + 4*q + tg);
            w1a2[q] = __ldg((const float2*)g_w1a + 4*q + tg);
            w1b2[q] = __ldg((const float2*)g_w1b + 4*q + tg);
            t12[q]  = __ldg((const float2*)g_t1  + 4*q + tg);
        }
        const float* of0p = Of + ((size_t)(b*2+0)*NUMK + k)*NN;
        const float* of1p = Of + ((size_t)(b*2+1)*NUMK + k)*NN;
        int use64 = g_args64;
        #pragma unroll
        for (int mt = 0; mt < 2; mt++)
        #pragma unroll
        for (int hh = 0; hh < 2; hh++) {
            int s = 32*w + 16*mt + 8*hh + g;
            int n = n0 + s;
            size_t ai = ((size_t)(b*NUMK + k))*NN + n;
            int j;
            if (use64) j = (int)__ldg((const long long*)args + ai);
            else       j = __ldg((const int*)args + ai);
            float pf = __ldg(Pf + (size_t)b*NN + j);
            pfs[mt*2 + hh] = pf;
            float2 pf2 = d2(pf);
            float2 o02 = d2(__ldg(of0p + n));
            float2 o12 = d2(__ldg(of1p + n));
            // permuted rows: thread tg's 8 channels are contiguous at +tg*8
            const float4* P4 = (const float4*)(g_P + ((size_t)(b*NN + n))*32 + tg*8);
            const float4* Q4 = (const float4*)(g_Q + ((size_t)(b*NN + j))*32 + tg*8);
            float4 pA = __ldg(P4),  pB = __ldg(P4 + 1);
            float4 qA = __ldg(Q4),  qB = __ldg(Q4 + 1);
            float2 pq[4], qq[4];
            pq[0] = make_float2(pA.x, pA.y); pq[1] = make_float2(pA.z, pA.w);
            pq[2] = make_float2(pB.x, pB.y); pq[3] = make_float2(pB.z, pB.w);
            qq[0] = make_float2(qA.x, qA.y); qq[1] = make_float2(qA.z, qA.w);
            qq[2] = make_float2(qB.x, qB.y); qq[3] = make_float2(qB.z, qB.w);
            #pragma unroll
            for (int q = 0; q < 4; q++) {
                float2 z = add2(add2(pq[q], qq[q]), t12[q]);
                z = fma2(w1p2[q], pf2, z);
                z = fma2(w1a2[q], o02, z);
                z = fma2(w1b2[q], o12, z);
                float2 r = gelu2(z);
                xa[mt*16 + q*4 + 2*hh]     = r.x;
                xa[mt*16 + q*4 + 2*hh + 1] = r.y;
            }
        }
    }

    layer_reg<false>(xa, xb, g_W2p, g_t2, nullptr, g, tg);   // h2 = xb
    layer_reg<false>(xb, xa, g_W3p, g_t3, nullptr, g, tg);   // l3 = xa
    layer_reg<true >(xa, xa, g_W4p, g_t4, xb,      g, tg);   // XF = gelu(h2 + bn4(W4 l3))

    // head: 3x32 dot per sample in packed pairs, reduce across tg-lanes
    {
        float2 wA2[4], wB2[4], wC2[4];
        #pragma unroll
        for (int nt = 0; nt < 4; nt++) {
            wA2[nt] = __ldg((const float2*)g_wcA + 4*nt + tg);
            wB2[nt] = __ldg((const float2*)g_wcB + 4*nt + tg);
            wC2[nt] = __ldg((const float2*)g_wcC + 4*nt + tg);
        }
        float bc0 = g_bcv[0], bc1 = g_bcv[1], bc2 = g_bcv[2];
        size_t obase = ((size_t)(b*NUMK + k))*NN + n0;
        #pragma unroll
        for (int mt = 0; mt < 2; mt++)
        #pragma unroll
        for (int hh = 0; hh < 2; hh++) {
            float2 a2 = d2(0.f), be2 = d2(0.f), om2 = d2(0.f);
            #pragma unroll
            for (int nt = 0; nt < 4; nt++) {
                float2 xp = make_float2(xa[mt*16 + nt*4 + 2*hh], xa[mt*16 + nt*4 + 2*hh + 1]);
                a2  = fma2(wA2[nt], xp, a2);
                be2 = fma2(wB2[nt], xp, be2);
                om2 = fma2(wC2[nt], xp, om2);
            }
            float a = a2.x + a2.y, be = be2.x + be2.y, om = om2.x + om2.y;
            a  += __shfl_xor_sync(0xffffffffu, a, 1);
            a  += __shfl_xor_sync(0xffffffffu, a, 2);
            be += __shfl_xor_sync(0xffffffffu, be, 1);
            be += __shfl_xor_sync(0xffffffffu, be, 2);
            om += __shfl_xor_sync(0xffffffffu, om, 1);
            om += __shfl_xor_sync(0xffffffffu, om, 2);
            if (tg == 0) {
                int s = 32*w + 16*mt + 8*hh + g;
                float U = (a + bc0 + 1.0f)*pfs[mt*2 + hh] + (be + bc1);
                g_U[obase + s]  = U;
                g_Om[obase + s] = om + bc2;
            }
        }
    }
}

// ---------------- kernel 4: softmax over NUM + weighted sum ----------------
__global__ void epi_kernel(float* __restrict__ out)
{
    int gid = blockIdx.x * blockDim.x + threadIdx.x;
    if (gid >= BB*NN) return;
    int b = gid / NN, n = gid % NN;
    size_t base = (size_t)b*NUMK*NN + n;
    float om[NUMK];
    float m = -3.4e38f;
    #pragma unroll
    for (int k = 0; k < NUMK; k++) {
        om[k] = g_Om[base + (size_t)k*NN];
        m = fmaxf(m, om[k]);
    }
    float num = 0.f, den = 0.f;
    #pragma unroll
    for (int k = 0; k < NUMK; k++) {
        float e = fex2((om[k] - m) * 1.4426950408889634f);
        den += e;
        num += e * g_U[base + (size_t)k*NN];
    }
    out[gid] = num * frcp(den);
}

// ---------------- launch ----------------
extern "C" void kernel_launch(void* const* d_in, const int* in_sizes, int n_in,
                              void* d_out, int out_size)
{
    const float* If = (const float*)d_in[0];
    const float* Pf = (const float*)d_in[1];
    const float* Of = (const float*)d_in[2];
    const void*  args = d_in[3];
    const float* W1 = (const float*)d_in[4];
    const float* g1 = (const float*)d_in[5];
    const float* b1 = (const float*)d_in[6];
    const float* m1 = (const float*)d_in[7];
    const float* v1 = (const float*)d_in[8];
    const float* W2 = (const float*)d_in[9];
    const float* g2 = (const float*)d_in[10];
    const float* b2 = (const float*)d_in[11];
    const float* m2 = (const float*)d_in[12];
    const float* v2 = (const float*)d_in[13];
    const float* W3 = (const float*)d_in[14];
    const float* g3 = (const float*)d_in[15];
    const float* b3 = (const float*)d_in[16];
    const float* m3 = (const float*)d_in[17];
    const float* v3 = (const float*)d_in[18];
    const float* W4 = (const float*)d_in[19];
    const float* g4 = (const float*)d_in[20];
    const float* b4 = (const float*)d_in[21];
    const float* m4 = (const float*)d_in[22];
    const float* v4 = (const float*)d_in[23];
    const float* Wc = (const float*)d_in[24];
    const float* bc = (const float*)d_in[25];

    prep_kernel<<<1, 256>>>(W1, g1, b1, m1, v1,
                            W2, g2, b2, m2, v2,
                            W3, g3, b3, m3, v3,
                            W4, g4, b4, m4, v4,
                            Wc, bc, (const int*)args);

    pq_kernel<<<BB*NT, 256>>>(If);

    main_kernel<<<BB*NUMK*NT, 256>>>(Pf, Of, args);

    epi_kernel<<<(BB*NN + 255)/256, 256>>>((float*)d_out);
}

// round 13
// speedup vs baseline: 1.0393x; 1.0260x over previous
#include <cuda_runtime.h>
#include <cuda_fp16.h>
#include <cstdint>

#define BB   2
#define CFI  32
#define HH   192
#define WWD  192
#define NN   (HH*WWD)        // 36864
#define NUMK 16
#define CT   67
#define EPSL 1e-5f
#define NT   (NN/256)        // 144 (pq tiles)
#define NT2  (NN/128)        // 288 (main tiles, 128 samples each)

// ---------------- scratch (static device globals; no allocation) ----------------
// g_P/g_Q rows are PERMUTED: within a row, channel c sits at
// p = ((c>>1)&3)*8 + ((c>>3)<<1) + (c&1)  (thread tg owns floats [tg*8, tg*8+8))
__device__ float g_P[BB*NN*CFI];
__device__ float g_Q[BB*NN*CFI];
__device__ float g_U[BB*NUMK*NN];
__device__ float g_Om[BB*NUMK*NN];

__device__ float g_WPQ[64*32];
__device__ float g_w1p[32], g_w1a[32], g_w1b[32], g_t1[32];
// packed f16x2 weights per layer: [k2][32] uint32 (single precision pass)
__device__ unsigned g_W2p[512];
__device__ unsigned g_W3p[512];
__device__ unsigned g_W4p[512];
__device__ float g_t2[32], g_t3[32], g_t4[32];
__device__ float g_wcA[32], g_wcB[32], g_wcC[32];
__device__ float g_bcv[3];
__device__ int   g_args64;

__device__ __forceinline__ float frcp(float x) { float y; asm("rcp.approx.f32 %0, %1;" : "=f"(y) : "f"(x)); return y; }
__device__ __forceinline__ float fex2(float x) { float y; asm("ex2.approx.f32 %0, %1;" : "=f"(y) : "f"(x)); return y; }

// ---------------- packed f32x2 helpers ----------------
__device__ __forceinline__ float2 fma2(float2 a, float2 b, float2 c) {
    float2 r;
    asm("fma.rn.f32x2 %0, %1, %2, %3;"
        : "=l"(*(unsigned long long*)&r)
        : "l"(*(const unsigned long long*)&a),
          "l"(*(const unsigned long long*)&b),
          "l"(*(const unsigned long long*)&c));
    return r;
}
__device__ __forceinline__ float2 mul2(float2 a, float2 b) {
    float2 r;
    asm("mul.rn.f32x2 %0, %1, %2;"
        : "=l"(*(unsigned long long*)&r)
        : "l"(*(const unsigned long long*)&a),
          "l"(*(const unsigned long long*)&b));
    return r;
}
__device__ __forceinline__ float2 add2(float2 a, float2 b) {
    float2 r;
    asm("add.rn.f32x2 %0, %1, %2;"
        : "=l"(*(unsigned long long*)&r)
        : "l"(*(const unsigned long long*)&a),
          "l"(*(const unsigned long long*)&b));
    return r;
}
__device__ __forceinline__ float2 d2(float v) { return make_float2(v, v); }

// packed fast gelu: 0.5*(x + |x|*erf(|x|/sqrt2)), erf via A&S 7.1.25 3-term
__device__ __forceinline__ float2 gelu2(float2 x) {
    unsigned long long ux = (*(unsigned long long*)&x) & 0x7FFFFFFF7FFFFFFFULL;
    float2 ax = *(float2*)&ux;
    float2 z  = mul2(ax, d2(0.70710678118654752f));
    float2 q  = fma2(z, d2(0.47047f), d2(1.0f));
    float2 t; t.x = frcp(q.x); t.y = frcp(q.y);
    float2 s  = mul2(mul2(z, z), d2(-1.4426950408889634f));
    float2 e; e.x = fex2(s.x); e.y = fex2(s.y);
    float2 h  = fma2(d2(0.7478556f), t, d2(-0.0958798f));
    h = fma2(h, t, d2(0.3480242f));
    h = mul2(h, t);
    float2 he = mul2(h, e);
    float2 E  = fma2(he, d2(-1.0f), d2(1.0f));
    float2 g  = mul2(ax, E);
    return mul2(add2(x, g), d2(0.5f));
}

// m16n8k16 fp16 MMA, row.col, fp32 accumulate in-place
__device__ __forceinline__ void mma16(float* d, unsigned a0, unsigned a1, unsigned a2, unsigned a3,
                                      unsigned b0, unsigned b1) {
    asm volatile(
        "mma.sync.aligned.m16n8k16.row.col.f32.f16.f16.f32 "
        "{%0,%1,%2,%3}, {%4,%5,%6,%7}, {%8,%9}, {%0,%1,%2,%3};"
        : "+f"(d[0]), "+f"(d[1]), "+f"(d[2]), "+f"(d[3])
        : "r"(a0), "r"(a1), "r"(a2), "r"(a3), "r"(b0), "r"(b1));
}

// ---------------- kernel 1: fold BN, pack fp16 weights, detect args dtype ----------------
__global__ void prep_kernel(
    const float* __restrict__ W1, const float* __restrict__ g1, const float* __restrict__ b1,
    const float* __restrict__ m1, const float* __restrict__ v1,
    const float* __restrict__ W2, const float* __restrict__ g2, const float* __restrict__ b2,
    const float* __restrict__ m2, const float* __restrict__ v2,
    const float* __restrict__ W3, const float* __restrict__ g3, const float* __restrict__ b3,
    const float* __restrict__ m3, const float* __restrict__ v3,
    const float* __restrict__ W4, const float* __restrict__ g4, const float* __restrict__ b4,
    const float* __restrict__ m4, const float* __restrict__ v4,
    const float* __restrict__ Wc, const float* __restrict__ bc,
    const int*   __restrict__ args_i32)
{
    __shared__ float inv1[32], inv2[32], inv3[32], inv4[32];
    int t = threadIdx.x;
    if (t < 32) {
        float i1 = g1[t]*rsqrtf(v1[t]+EPSL); inv1[t]=i1; g_t1[t]=b1[t]-m1[t]*i1;
        float i2 = g2[t]*rsqrtf(v2[t]+EPSL); inv2[t]=i2; g_t2[t]=b2[t]-m2[t]*i2;
        float i3 = g3[t]*rsqrtf(v3[t]+EPSL); inv3[t]=i3; g_t3[t]=b3[t]-m3[t]*i3;
        float i4 = g4[t]*rsqrtf(v4[t]+EPSL); inv4[t]=i4; g_t4[t]=b4[t]-m4[t]*i4;
        g_wcA[t]=Wc[t]; g_wcB[t]=Wc[32+t]; g_wcC[t]=Wc[64+t];
        g_w1p[t]=W1[t*CT+64]*i1; g_w1a[t]=W1[t*CT+65]*i1; g_w1b[t]=W1[t*CT+66]*i1;
    }
    if (t < 3) g_bcv[t] = bc[t];
    if (t == 0) {
        int all_zero = 1;
        for (int i = 0; i < 128; i++) if (args_i32[2*i+1] != 0) { all_zero = 0; break; }
        g_args64 = all_zero;
    }
    __syncthreads();
    for (int idx = t; idx < 2048; idx += blockDim.x) {
        int r = idx >> 5, i = idx & 31;
        g_WPQ[idx] = (r < 32) ? W1[r*CT + i] * inv1[r]
                              : W1[(r-32)*CT + 32 + i] * inv1[r-32];
    }
    for (int idx = t; idx < 512; idx += blockDim.x) {
        int k2 = idx >> 5, n = idx & 31;
        __half2 p;
        p = __floats2half2_rn(W2[n*32 + 2*k2]*inv2[n], W2[n*32 + 2*k2 + 1]*inv2[n]);
        g_W2p[idx] = *(unsigned*)&p;
        p = __floats2half2_rn(W3[n*32 + 2*k2]*inv3[n], W3[n*32 + 2*k2 + 1]*inv3[n]);
        g_W3p[idx] = *(unsigned*)&p;
        p = __floats2half2_rn(W4[n*32 + 2*k2]*inv4[n], W4[n*32 + 2*k2 + 1]*inv4[n]);
        g_W4p[idx] = *(unsigned*)&p;
    }
}

// channel -> permuted position within a 32-float P/Q row
__device__ __forceinline__ int permc(int c) {
    return ((c >> 1) & 3) * 8 + ((c >> 3) << 1) + (c & 1);
}

// ---------------- kernel 2: P/Q = folded-W1 @ If, permuted [b][n][p] ----------------
__global__ void pq_kernel(const float* __restrict__ If)
{
    __shared__ float wf[2048];
    __shared__ float tb[256*33];
    int tid  = threadIdx.x;
    int b    = blockIdx.x / NT;
    int tile = blockIdx.x % NT;
    int n0   = tile * 256;

    for (int idx = tid; idx < 2048; idx += 256) wf[idx] = g_WPQ[idx];

    int n = n0 + tid;
    float x[32];
    #pragma unroll
    for (int i = 0; i < 32; i++) x[i] = If[((size_t)b*32 + i)*NN + n];
    __syncthreads();

    size_t base = ((size_t)b*NN + n0) * 32;

    #pragma unroll
    for (int c = 0; c < 32; c++) {
        float acc = 0.f;
        #pragma unroll
        for (int i = 0; i < 32; i += 4) {
            float4 w = *(const float4*)&wf[c*32 + i];
            acc += w.x*x[i] + w.y*x[i+1] + w.z*x[i+2] + w.w*x[i+3];
        }
        tb[tid*33 + c] = acc;
    }
    __syncthreads();
    for (int idx = tid; idx < 8192; idx += 256)
        g_P[base + (idx & ~31) + permc(idx & 31)] = tb[(idx >> 5)*33 + (idx & 31)];
    __syncthreads();

    #pragma unroll
    for (int c = 0; c < 32; c++) {
        float acc = 0.f;
        #pragma unroll
        for (int i = 0; i < 32; i += 4) {
            float4 w = *(const float4*)&wf[(32+c)*32 + i];
            acc += w.x*x[i] + w.y*x[i+1] + w.z*x[i+2] + w.w*x[i+3];
        }
        tb[tid*33 + c] = acc;
    }
    __syncthreads();
    for (int idx = tid; idx < 8192; idx += 256)
        g_Q[base + (idx & ~31) + permc(idx & 31)] = tb[(idx >> 5)*33 + (idx & 31)];
}

// ---------------- register-resident MLP layer (single m16 tile per warp) ----------------
// x layout: x[nt*4 + 2*hh + par], channel = 8*nt + 2*tg + par, row = g + 8*hh
template<bool ADD>
__device__ __forceinline__ void layer_reg(
    const float* xin, float* xout,
    const unsigned* __restrict__ wp, const float* __restrict__ bias,
    const float* resid, int g, int tg)
{
    // pack activations to fp16: ah[kg*2 + hh] = channels {8kg+2tg, +1}, row g+8hh
    unsigned ah[8];
    #pragma unroll
    for (int nt = 0; nt < 4; nt++) {
        #pragma unroll
        for (int hh = 0; hh < 2; hh++) {
            __half2 p = __floats2half2_rn(xin[nt*4 + 2*hh], xin[nt*4 + 2*hh + 1]);
            ah[nt*2 + hh] = *(unsigned*)&p;
        }
    }
    // init accumulators with bias
    float d[16];
    #pragma unroll
    for (int nt = 0; nt < 4; nt++) {
        float2 bv = __ldg((const float2*)bias + 4*nt + tg);
        d[nt*4 + 0] = bv.x; d[nt*4 + 1] = bv.y;
        d[nt*4 + 2] = bv.x; d[nt*4 + 3] = bv.y;
    }
    // mma mainloop: 2 k-steps x 4 n-tiles
    #pragma unroll
    for (int ks = 0; ks < 2; ks++) {
        #pragma unroll
        for (int nt = 0; nt < 4; nt++) {
            unsigned b0 = __ldg(wp + (ks*8 + tg    )*32 + 8*nt + g);
            unsigned b1 = __ldg(wp + (ks*8 + tg + 4)*32 + 8*nt + g);
            mma16(d + nt*4, ah[4*ks], ah[4*ks+1], ah[4*ks+2], ah[4*ks+3], b0, b1);
        }
    }
    // packed-pair gelu epilogue
    #pragma unroll
    for (int i = 0; i < 16; i += 2) {
        float2 v = make_float2(d[i], d[i+1]);
        if (ADD) v = add2(v, make_float2(resid[i], resid[i+1]));
        float2 r = gelu2(v);
        xout[i] = r.x; xout[i+1] = r.y;
    }
}

// ---------------- kernel 3: main fused MLP, 16 samples per warp ----------------
__global__ void __launch_bounds__(256) main_kernel(
    const float* __restrict__ Pf,
    const float* __restrict__ Of,
    const void*  __restrict__ args)
{
    int bk   = blockIdx.x / NT2;
    int tile = blockIdx.x % NT2;
    int b = bk / NUMK, k = bk % NUMK;
    int n0 = tile * 128;
    int tid = threadIdx.x;
    int w = tid >> 5, lane = tid & 31;
    int g = lane >> 2, tg = lane & 3;

    float xa[16], xb[16];
    float pfs[2];

    // stage 1: h1 in D-frag register layout (packed math + vectorized P/Q loads)
    {
        float2 w1p2[4], w1a2[4], w1b2[4], t12[4];
        #pragma unroll
        for (int q = 0; q < 4; q++) {
            w1p2[q] = __ldg((const float2*)g_w1p + 4*q + tg);
            w1a2[q] = __ldg((const float2*)g_w1a + 4*q + tg);
            w1b2[q] = __ldg((const float2*)g_w1b + 4*q + tg);
            t12[q]  = __ldg((const float2*)g_t1  + 4*q + tg);
        }
        const float* of0p = Of + ((size_t)(b*2+0)*NUMK + k)*NN;
        const float* of1p = Of + ((size_t)(b*2+1)*NUMK + k)*NN;
        int use64 = g_args64;
        #pragma unroll
        for (int hh = 0; hh < 2; hh++) {
            int s = w*16 + 8*hh + g;
            int n = n0 + s;
            size_t ai = ((size_t)(b*NUMK + k))*NN + n;
            int j;
            if (use64) j = (int)__ldg((const long long*)args + ai);
            else       j = __ldg((const int*)args + ai);
            float pf = __ldg(Pf + (size_t)b*NN + j);
            pfs[hh] = pf;
            float2 pf2 = d2(pf);
            float2 o02 = d2(__ldg(of0p + n));
            float2 o12 = d2(__ldg(of1p + n));
            const float4* P4 = (const float4*)(g_P + ((size_t)(b*NN + n))*32 + tg*8);
            const float4* Q4 = (const float4*)(g_Q + ((size_t)(b*NN + j))*32 + tg*8);
            float4 pA = __ldg(P4),  pB = __ldg(P4 + 1);
            float4 qA = __ldg(Q4),  qB = __ldg(Q4 + 1);
            float2 pq[4], qq[4];
            pq[0] = make_float2(pA.x, pA.y); pq[1] = make_float2(pA.z, pA.w);
            pq[2] = make_float2(pB.x, pB.y); pq[3] = make_float2(pB.z, pB.w);
            qq[0] = make_float2(qA.x, qA.y); qq[1] = make_float2(qA.z, qA.w);
            qq[2] = make_float2(qB.x, qB.y); qq[3] = make_float2(qB.z, qB.w);
            #pragma unroll
            for (int q = 0; q < 4; q++) {
                float2 z = add2(add2(pq[q], qq[q]), t12[q]);
                z = fma2(w1p2[q], pf2, z);
                z = fma2(w1a2[q], o02, z);
                z = fma2(w1b2[q], o12, z);
                float2 r = gelu2(z);
                xa[q*4 + 2*hh]     = r.x;
                xa[q*4 + 2*hh + 1] = r.y;
            }
        }
    }

    layer_reg<false>(xa, xb, g_W2p, g_t2, nullptr, g, tg);   // h2 = xb
    layer_reg<false>(xb, xa, g_W3p, g_t3, nullptr, g, tg);   // l3 = xa
    layer_reg<true >(xa, xa, g_W4p, g_t4, xb,      g, tg);   // XF = gelu(h2 + bn4(W4 l3))

    // head: 3x32 dot per sample in packed pairs, reduce across tg-lanes
    {
        float2 wA2[4], wB2[4], wC2[4];
        #pragma unroll
        for (int nt = 0; nt < 4; nt++) {
            wA2[nt] = __ldg((const float2*)g_wcA + 4*nt + tg);
            wB2[nt] = __ldg((const float2*)g_wcB + 4*nt + tg);
            wC2[nt] = __ldg((const float2*)g_wcC + 4*nt + tg);
        }
        float bc0 = g_bcv[0], bc1 = g_bcv[1], bc2 = g_bcv[2];
        size_t obase = ((size_t)(b*NUMK + k))*NN + n0;
        #pragma unroll
        for (int hh = 0; hh < 2; hh++) {
            float2 a2 = d2(0.f), be2 = d2(0.f), om2 = d2(0.f);
            #pragma unroll
            for (int nt = 0; nt < 4; nt++) {
                float2 xp = make_float2(xa[nt*4 + 2*hh], xa[nt*4 + 2*hh + 1]);
                a2  = fma2(wA2[nt], xp, a2);
                be2 = fma2(wB2[nt], xp, be2);
                om2 = fma2(wC2[nt], xp, om2);
            }
            float a = a2.x + a2.y, be = be2.x + be2.y, om = om2.x + om2.y;
            a  += __shfl_xor_sync(0xffffffffu, a, 1);
            a  += __shfl_xor_sync(0xffffffffu, a, 2);
            be += __shfl_xor_sync(0xffffffffu, be, 1);
            be += __shfl_xor_sync(0xffffffffu, be, 2);
            om += __shfl_xor_sync(0xffffffffu, om, 1);
            om += __shfl_xor_sync(0xffffffffu, om, 2);
            if (tg == 0) {
                int s = w*16 + 8*hh + g;
                float U = (a + bc0 + 1.0f)*pfs[hh] + (be + bc1);
                g_U[obase + s]  = U;
                g_Om[obase + s] = om + bc2;
            }
        }
    }
}

// ---------------- kernel 4: softmax over NUM + weighted sum ----------------
__global__ void epi_kernel(float* __restrict__ out)
{
    int gid = blockIdx.x * blockDim.x + threadIdx.x;
    if (gid >= BB*NN) return;
    int b = gid / NN, n = gid % NN;
    size_t base = (size_t)b*NUMK*NN + n;
    float om[NUMK];
    float m = -3.4e38f;
    #pragma unroll
    for (int k = 0; k < NUMK; k++) {
        om[k] = g_Om[base + (size_t)k*NN];
        m = fmaxf(m, om[k]);
    }
    float num = 0.f, den = 0.f;
    #pragma unroll
    for (int k = 0; k < NUMK; k++) {
        float e = fex2((om[k] - m) * 1.4426950408889634f);
        den += e;
        num += e * g_U[base + (size_t)k*NN];
    }
    out[gid] = num * frcp(den);
}

// ---------------- launch ----------------
extern "C" void kernel_launch(void* const* d_in, const int* in_sizes, int n_in,
                              void* d_out, int out_size)
{
    const float* If = (const float*)d_in[0];
    const float* Pf = (const float*)d_in[1];
    const float* Of = (const float*)d_in[2];
    const void*  args = d_in[3];
    const float* W1 = (const float*)d_in[4];
    const float* g1 = (const float*)d_in[5];
    const float* b1 = (const float*)d_in[6];
    const float* m1 = (const float*)d_in[7];
    const float* v1 = (const float*)d_in[8];
    const float* W2 = (const float*)d_in[9];
    const float* g2 = (const float*)d_in[10];
    const float* b2 = (const float*)d_in[11];
    const float* m2 = (const float*)d_in[12];
    const float* v2 = (const float*)d_in[13];
    const float* W3 = (const float*)d_in[14];
    const float* g3 = (const float*)d_in[15];
    const float* b3 = (const float*)d_in[16];
    const float* m3 = (const float*)d_in[17];
    const float* v3 = (const float*)d_in[18];
    const float* W4 = (const float*)d_in[19];
    const float* g4 = (const float*)d_in[20];
    const float* b4 = (const float*)d_in[21];
    const float* m4 = (const float*)d_in[22];
    const float* v4 = (const float*)d_in[23];
    const float* Wc = (const float*)d_in[24];
    const float* bc = (const float*)d_in[25];

    prep_kernel<<<1, 256>>>(W1, g1, b1, m1, v1,
                            W2, g2, b2, m2, v2,
                            W3, g3, b3, m3, v3,
                            W4, g4, b4, m4, v4,
                            Wc, bc, (const int*)args);

    pq_kernel<<<BB*NT, 256>>>(If);

    main_kernel<<<BB*NUMK*NT2, 256>>>(Pf, Of, args);

    epi_kernel<<<(BB*NN + 255)/256, 256>>>((float*)d_out);
}

// round 14
// speedup vs baseline: 1.0673x; 1.0269x over previous
#include <cuda_runtime.h>
#include <cuda_fp16.h>
#include <cstdint>

#define BB   2
#define CFI  32
#define HH   192
#define WWD  192
#define NN   (HH*WWD)        // 36864
#define NUMK 16
#define CT   67
#define EPSL 1e-5f
#define NT   (NN/256)        // 144 (pq tiles)
#define NB2  (NN/8)          // 4608 main tiles: 8 samples x 16 k per block

// ---------------- scratch (static device globals; no allocation) ----------------
// g_P/g_Q rows are PERMUTED: within a row, channel c sits at
// p = ((c>>1)&3)*8 + ((c>>3)<<1) + (c&1)  (thread tg owns floats [tg*8, tg*8+8))
__device__ float g_P[BB*NN*CFI];
__device__ float g_Q[BB*NN*CFI];

__device__ float g_WPQ[64*32];
__device__ float g_w1p[32], g_w1a[32], g_w1b[32], g_t1[32];
// packed f16x2 weights per layer: [k2][32] uint32 (single precision pass)
__device__ unsigned g_W2p[512];
__device__ unsigned g_W3p[512];
__device__ unsigned g_W4p[512];
__device__ float g_t2[32], g_t3[32], g_t4[32];
__device__ float g_wcA[32], g_wcB[32], g_wcC[32];
__device__ float g_bcv[3];
__device__ int   g_args64;

__device__ __forceinline__ float frcp(float x) { float y; asm("rcp.approx.f32 %0, %1;" : "=f"(y) : "f"(x)); return y; }
__device__ __forceinline__ float fex2(float x) { float y; asm("ex2.approx.f32 %0, %1;" : "=f"(y) : "f"(x)); return y; }

// ---------------- packed f32x2 helpers ----------------
__device__ __forceinline__ float2 fma2(float2 a, float2 b, float2 c) {
    float2 r;
    asm("fma.rn.f32x2 %0, %1, %2, %3;"
        : "=l"(*(unsigned long long*)&r)
        : "l"(*(const unsigned long long*)&a),
          "l"(*(const unsigned long long*)&b),
          "l"(*(const unsigned long long*)&c));
    return r;
}
__device__ __forceinline__ float2 mul2(float2 a, float2 b) {
    float2 r;
    asm("mul.rn.f32x2 %0, %1, %2;"
        : "=l"(*(unsigned long long*)&r)
        : "l"(*(const unsigned long long*)&a),
          "l"(*(const unsigned long long*)&b));
    return r;
}
__device__ __forceinline__ float2 add2(float2 a, float2 b) {
    float2 r;
    asm("add.rn.f32x2 %0, %1, %2;"
        : "=l"(*(unsigned long long*)&r)
        : "l"(*(const unsigned long long*)&a),
          "l"(*(const unsigned long long*)&b));
    return r;
}
__device__ __forceinline__ float2 d2(float v) { return make_float2(v, v); }

// packed fast gelu: 0.5*(x + |x|*erf(|x|/sqrt2)), erf via A&S 7.1.25 3-term
__device__ __forceinline__ float2 gelu2(float2 x) {
    unsigned long long ux = (*(unsigned long long*)&x) & 0x7FFFFFFF7FFFFFFFULL;
    float2 ax = *(float2*)&ux;
    float2 z  = mul2(ax, d2(0.70710678118654752f));
    float2 q  = fma2(z, d2(0.47047f), d2(1.0f));
    float2 t; t.x = frcp(q.x); t.y = frcp(q.y);
    float2 s  = mul2(mul2(z, z), d2(-1.4426950408889634f));
    float2 e; e.x = fex2(s.x); e.y = fex2(s.y);
    float2 h  = fma2(d2(0.7478556f), t, d2(-0.0958798f));
    h = fma2(h, t, d2(0.3480242f));
    h = mul2(h, t);
    float2 he = mul2(h, e);
    float2 E  = fma2(he, d2(-1.0f), d2(1.0f));
    float2 g  = mul2(ax, E);
    return mul2(add2(x, g), d2(0.5f));
}

// m16n8k16 fp16 MMA, row.col, fp32 accumulate in-place
__device__ __forceinline__ void mma16(float* d, unsigned a0, unsigned a1, unsigned a2, unsigned a3,
                                      unsigned b0, unsigned b1) {
    asm volatile(
        "mma.sync.aligned.m16n8k16.row.col.f32.f16.f16.f32 "
        "{%0,%1,%2,%3}, {%4,%5,%6,%7}, {%8,%9}, {%0,%1,%2,%3};"
        : "+f"(d[0]), "+f"(d[1]), "+f"(d[2]), "+f"(d[3])
        : "r"(a0), "r"(a1), "r"(a2), "r"(a3), "r"(b0), "r"(b1));
}

// ---------------- kernel 1: fold BN, pack fp16 weights, detect args dtype ----------------
__global__ void prep_kernel(
    const float* __restrict__ W1, const float* __restrict__ g1, const float* __restrict__ b1,
    const float* __restrict__ m1, const float* __restrict__ v1,
    const float* __restrict__ W2, const float* __restrict__ g2, const float* __restrict__ b2,
    const float* __restrict__ m2, const float* __restrict__ v2,
    const float* __restrict__ W3, const float* __restrict__ g3, const float* __restrict__ b3,
    const float* __restrict__ m3, const float* __restrict__ v3,
    const float* __restrict__ W4, const float* __restrict__ g4, const float* __restrict__ b4,
    const float* __restrict__ m4, const float* __restrict__ v4,
    const float* __restrict__ Wc, const float* __restrict__ bc,
    const int*   __restrict__ args_i32)
{
    __shared__ float inv1[32], inv2[32], inv3[32], inv4[32];
    int t = threadIdx.x;
    if (t < 32) {
        float i1 = g1[t]*rsqrtf(v1[t]+EPSL); inv1[t]=i1; g_t1[t]=b1[t]-m1[t]*i1;
        float i2 = g2[t]*rsqrtf(v2[t]+EPSL); inv2[t]=i2; g_t2[t]=b2[t]-m2[t]*i2;
        float i3 = g3[t]*rsqrtf(v3[t]+EPSL); inv3[t]=i3; g_t3[t]=b3[t]-m3[t]*i3;
        float i4 = g4[t]*rsqrtf(v4[t]+EPSL); inv4[t]=i4; g_t4[t]=b4[t]-m4[t]*i4;
        g_wcA[t]=Wc[t]; g_wcB[t]=Wc[32+t]; g_wcC[t]=Wc[64+t];
        g_w1p[t]=W1[t*CT+64]*i1; g_w1a[t]=W1[t*CT+65]*i1; g_w1b[t]=W1[t*CT+66]*i1;
    }
    if (t < 3) g_bcv[t] = bc[t];
    if (t == 0) {
        int all_zero = 1;
        for (int i = 0; i < 128; i++) if (args_i32[2*i+1] != 0) { all_zero = 0; break; }
        g_args64 = all_zero;
    }
    __syncthreads();
    for (int idx = t; idx < 2048; idx += blockDim.x) {
        int r = idx >> 5, i = idx & 31;
        g_WPQ[idx] = (r < 32) ? W1[r*CT + i] * inv1[r]
                              : W1[(r-32)*CT + 32 + i] * inv1[r-32];
    }
    for (int idx = t; idx < 512; idx += blockDim.x) {
        int k2 = idx >> 5, n = idx & 31;
        __half2 p;
        p = __floats2half2_rn(W2[n*32 + 2*k2]*inv2[n], W2[n*32 + 2*k2 + 1]*inv2[n]);
        g_W2p[idx] = *(unsigned*)&p;
        p = __floats2half2_rn(W3[n*32 + 2*k2]*inv3[n], W3[n*32 + 2*k2 + 1]*inv3[n]);
        g_W3p[idx] = *(unsigned*)&p;
        p = __floats2half2_rn(W4[n*32 + 2*k2]*inv4[n], W4[n*32 + 2*k2 + 1]*inv4[n]);
        g_W4p[idx] = *(unsigned*)&p;
    }
}

// channel -> permuted position within a 32-float P/Q row
__device__ __forceinline__ int permc(int c) {
    return ((c >> 1) & 3) * 8 + ((c >> 3) << 1) + (c & 1);
}

// ---------------- kernel 2: P/Q = folded-W1 @ If, permuted [b][n][p] ----------------
__global__ void pq_kernel(const float* __restrict__ If)
{
    __shared__ float wf[2048];
    __shared__ float tb[256*33];
    int tid  = threadIdx.x;
    int b    = blockIdx.x / NT;
    int tile = blockIdx.x % NT;
    int n0   = tile * 256;

    for (int idx = tid; idx < 2048; idx += 256) wf[idx] = g_WPQ[idx];

    int n = n0 + tid;
    float x[32];
    #pragma unroll
    for (int i = 0; i < 32; i++) x[i] = If[((size_t)b*32 + i)*NN + n];
    __syncthreads();

    size_t base = ((size_t)b*NN + n0) * 32;

    #pragma unroll
    for (int c = 0; c < 32; c++) {
        float acc = 0.f;
        #pragma unroll
        for (int i = 0; i < 32; i += 4) {
            float4 w = *(const float4*)&wf[c*32 + i];
            acc += w.x*x[i] + w.y*x[i+1] + w.z*x[i+2] + w.w*x[i+3];
        }
        tb[tid*33 + c] = acc;
    }
    __syncthreads();
    for (int idx = tid; idx < 8192; idx += 256)
        g_P[base + (idx & ~31) + permc(idx & 31)] = tb[(idx >> 5)*33 + (idx & 31)];
    __syncthreads();

    #pragma unroll
    for (int c = 0; c < 32; c++) {
        float acc = 0.f;
        #pragma unroll
        for (int i = 0; i < 32; i += 4) {
            float4 w = *(const float4*)&wf[(32+c)*32 + i];
            acc += w.x*x[i] + w.y*x[i+1] + w.z*x[i+2] + w.w*x[i+3];
        }
        tb[tid*33 + c] = acc;
    }
    __syncthreads();
    for (int idx = tid; idx < 8192; idx += 256)
        g_Q[base + (idx & ~31) + permc(idx & 31)] = tb[(idx >> 5)*33 + (idx & 31)];
}

// ---------------- register-resident MLP layer (single m16 tile per warp) ----------------
// x layout: x[nt*4 + 2*hh + par], channel = 8*nt + 2*tg + par, row = g + 8*hh
template<bool ADD>
__device__ __forceinline__ void layer_reg(
    const float* xin, float* xout,
    const unsigned* __restrict__ wp, const float* __restrict__ bias,
    const float* resid, int g, int tg)
{
    unsigned ah[8];
    #pragma unroll
    for (int nt = 0; nt < 4; nt++) {
        #pragma unroll
        for (int hh = 0; hh < 2; hh++) {
            __half2 p = __floats2half2_rn(xin[nt*4 + 2*hh], xin[nt*4 + 2*hh + 1]);
            ah[nt*2 + hh] = *(unsigned*)&p;
        }
    }
    float d[16];
    #pragma unroll
    for (int nt = 0; nt < 4; nt++) {
        float2 bv = __ldg((const float2*)bias + 4*nt + tg);
        d[nt*4 + 0] = bv.x; d[nt*4 + 1] = bv.y;
        d[nt*4 + 2] = bv.x; d[nt*4 + 3] = bv.y;
    }
    #pragma unroll
    for (int ks = 0; ks < 2; ks++) {
        #pragma unroll
        for (int nt = 0; nt < 4; nt++) {
            unsigned b0 = __ldg(wp + (ks*8 + tg    )*32 + 8*nt + g);
            unsigned b1 = __ldg(wp + (ks*8 + tg + 4)*32 + 8*nt + g);
            mma16(d + nt*4, ah[4*ks], ah[4*ks+1], ah[4*ks+2], ah[4*ks+3], b0, b1);
        }
    }
    #pragma unroll
    for (int i = 0; i < 16; i += 2) {
        float2 v = make_float2(d[i], d[i+1]);
        if (ADD) v = add2(v, make_float2(resid[i], resid[i+1]));
        float2 r = gelu2(v);
        xout[i] = r.x; xout[i+1] = r.y;
    }
}

// ---------------- kernel 3: fused MLP + softmax epilogue ----------------
// block: 8 samples x 16 k. warp w: rows 0-7 = k0=2w, rows 8-15 = k=2w+1, sample n0+g.
__global__ void __launch_bounds__(256) main_kernel(
    const float* __restrict__ Pf,
    const float* __restrict__ Of,
    const void*  __restrict__ args,
    float* __restrict__ out)
{
    __shared__ float sU[NUMK][8];
    __shared__ float sOm[NUMK][8];

    int b  = blockIdx.x / NB2;
    int n0 = (blockIdx.x % NB2) * 8;
    int tid = threadIdx.x;
    int w = tid >> 5, lane = tid & 31;
    int g = lane >> 2, tg = lane & 3;

    float xa[16], xb[16];
    float pfs[2];
    int n = n0 + g;                       // this warp-lane-group's sample

    // stage 1: h1 in D-frag register layout; hh selects k = 2w+hh
    {
        float2 w1p2[4], w1a2[4], w1b2[4], t12[4];
        #pragma unroll
        for (int q = 0; q < 4; q++) {
            w1p2[q] = __ldg((const float2*)g_w1p + 4*q + tg);
            w1a2[q] = __ldg((const float2*)g_w1a + 4*q + tg);
            w1b2[q] = __ldg((const float2*)g_w1b + 4*q + tg);
            t12[q]  = __ldg((const float2*)g_t1  + 4*q + tg);
        }
        int use64 = g_args64;
        const float4* P4 = (const float4*)(g_P + ((size_t)(b*NN + n))*32 + tg*8);
        float4 pA = __ldg(P4), pB = __ldg(P4 + 1);
        float2 pq[4];
        pq[0] = make_float2(pA.x, pA.y); pq[1] = make_float2(pA.z, pA.w);
        pq[2] = make_float2(pB.x, pB.y); pq[3] = make_float2(pB.z, pB.w);
        #pragma unroll
        for (int hh = 0; hh < 2; hh++) {
            int k = 2*w + hh;
            size_t ai = ((size_t)(b*NUMK + k))*NN + n;
            int j;
            if (use64) j = (int)__ldg((const long long*)args + ai);
            else       j = __ldg((const int*)args + ai);
            float pf = __ldg(Pf + (size_t)b*NN + j);
            pfs[hh] = pf;
            float2 pf2 = d2(pf);
            float2 o02 = d2(__ldg(Of + ((size_t)(b*2+0)*NUMK + k)*NN + n));
            float2 o12 = d2(__ldg(Of + ((size_t)(b*2+1)*NUMK + k)*NN + n));
            const float4* Q4 = (const float4*)(g_Q + ((size_t)(b*NN + j))*32 + tg*8);
            float4 qA = __ldg(Q4), qB = __ldg(Q4 + 1);
            float2 qq[4];
            qq[0] = make_float2(qA.x, qA.y); qq[1] = make_float2(qA.z, qA.w);
            qq[2] = make_float2(qB.x, qB.y); qq[3] = make_float2(qB.z, qB.w);
            #pragma unroll
            for (int q = 0; q < 4; q++) {
                float2 z = add2(add2(pq[q], qq[q]), t12[q]);
                z = fma2(w1p2[q], pf2, z);
                z = fma2(w1a2[q], o02, z);
                z = fma2(w1b2[q], o12, z);
                float2 r = gelu2(z);
                xa[q*4 + 2*hh]     = r.x;
                xa[q*4 + 2*hh + 1] = r.y;
            }
        }
    }

    layer_reg<false>(xa, xb, g_W2p, g_t2, nullptr, g, tg);   // h2 = xb
    layer_reg<false>(xb, xa, g_W3p, g_t3, nullptr, g, tg);   // l3 = xa
    layer_reg<true >(xa, xa, g_W4p, g_t4, xb,      g, tg);   // XF = gelu(h2 + bn4(W4 l3))

    // head: 3x32 dot per (k, n), reduce across tg-lanes, deposit U/Om in smem
    {
        float2 wA2[4], wB2[4], wC2[4];
        #pragma unroll
        for (int nt = 0; nt < 4; nt++) {
            wA2[nt] = __ldg((const float2*)g_wcA + 4*nt + tg);
            wB2[nt] = __ldg((const float2*)g_wcB + 4*nt + tg);
            wC2[nt] = __ldg((const float2*)g_wcC + 4*nt + tg);
        }
        float bc0 = g_bcv[0], bc1 = g_bcv[1], bc2 = g_bcv[2];
        #pragma unroll
        for (int hh = 0; hh < 2; hh++) {
            float2 a2 = d2(0.f), be2 = d2(0.f), om2 = d2(0.f);
            #pragma unroll
            for (int nt = 0; nt < 4; nt++) {
                float2 xp = make_float2(xa[nt*4 + 2*hh], xa[nt*4 + 2*hh + 1]);
                a2  = fma2(wA2[nt], xp, a2);
                be2 = fma2(wB2[nt], xp, be2);
                om2 = fma2(wC2[nt], xp, om2);
            }
            float a = a2.x + a2.y, be = be2.x + be2.y, om = om2.x + om2.y;
            a  += __shfl_xor_sync(0xffffffffu, a, 1);
            a  += __shfl_xor_sync(0xffffffffu, a, 2);
            be += __shfl_xor_sync(0xffffffffu, be, 1);
            be += __shfl_xor_sync(0xffffffffu, be, 2);
            om += __shfl_xor_sync(0xffffffffu, om, 1);
            om += __shfl_xor_sync(0xffffffffu, om, 2);
            if (tg == 0) {
                int k = 2*w + hh;
                sU[k][g]  = (a + bc0 + 1.0f)*pfs[hh] + (be + bc1);
                sOm[k][g] = om + bc2;
            }
        }
    }
    __syncthreads();

    // softmax over k + weighted sum; threads 0-7 each own one sample
    if (tid < 8) {
        float om[NUMK];
        float m = -3.4e38f;
        #pragma unroll
        for (int k = 0; k < NUMK; k++) {
            om[k] = sOm[k][tid];
            m = fmaxf(m, om[k]);
        }
        float num = 0.f, den = 0.f;
        #pragma unroll
        for (int k = 0; k < NUMK; k++) {
            float e = fex2((om[k] - m) * 1.4426950408889634f);
            den += e;
            num += e * sU[k][tid];
        }
        out[(size_t)b*NN + n0 + tid] = num * frcp(den);
    }
}

// ---------------- launch ----------------
extern "C" void kernel_launch(void* const* d_in, const int* in_sizes, int n_in,
                              void* d_out, int out_size)
{
    const float* If = (const float*)d_in[0];
    const float* Pf = (const float*)d_in[1];
    const float* Of = (const float*)d_in[2];
    const void*  args = d_in[3];
    const float* W1 = (const float*)d_in[4];
    const float* g1 = (const float*)d_in[5];
    const float* b1 = (const float*)d_in[6];
    const float* m1 = (const float*)d_in[7];
    const float* v1 = (const float*)d_in[8];
    const float* W2 = (const float*)d_in[9];
    const float* g2 = (const float*)d_in[10];
    const float* b2 = (const float*)d_in[11];
    const float* m2 = (const float*)d_in[12];
    const float* v2 = (const float*)d_in[13];
    const float* W3 = (const float*)d_in[14];
    const float* g3 = (const float*)d_in[15];
    const float* b3 = (const float*)d_in[16];
    const float* m3 = (const float*)d_in[17];
    const float* v3 = (const float*)d_in[18];
    const float* W4 = (const float*)d_in[19];
    const float* g4 = (const float*)d_in[20];
    const float* b4 = (const float*)d_in[21];
    const float* m4 = (const float*)d_in[22];
    const float* v4 = (const float*)d_in[23];
    const float* Wc = (const float*)d_in[24];
    const float* bc = (const float*)d_in[25];

    prep_kernel<<<1, 256>>>(W1, g1, b1, m1, v1,
                            W2, g2, b2, m2, v2,
                            W3, g3, b3, m3, v3,
                            W4, g4, b4, m4, v4,
                            Wc, bc, (const int*)args);

    pq_kernel<<<BB*NT, 256>>>(If);

    main_kernel<<<BB*NB2, 256>>>(Pf, Of, args, (float*)d_out);
}

// round 15
// speedup vs baseline: 1.0971x; 1.0279x over previous
#include <cuda_runtime.h>
#include <cuda_fp16.h>
#include <cstdint>

#define BB   2
#define CFI  32
#define HH   192
#define WWD  192
#define NN   (HH*WWD)        // 36864
#define NUMK 16
#define CT   67
#define EPSL 1e-5f
#define NT   (NN/256)        // 144 (pq tiles)
#define NB2  (NN/8)          // 4608 main tiles: 8 samples x 16 k per block

// ---------------- scratch (static device globals; no allocation) ----------------
// g_P/g_Q rows are PERMUTED: within a row, channel c sits at
// p = ((c>>1)&3)*8 + ((c>>3)<<1) + (c&1)  (thread tg owns floats [tg*8, tg*8+8))
__device__ float g_P[BB*NN*CFI];
__device__ float g_Q[BB*NN*CFI];

__device__ float g_w1p[32], g_w1a[32], g_w1b[32], g_t1[32];
// packed f16x2 weights per layer: [k2][32] uint32 (single precision pass)
__device__ unsigned g_W2p[512];
__device__ unsigned g_W3p[512];
__device__ unsigned g_W4p[512];
__device__ float g_t2[32], g_t3[32], g_t4[32];
__device__ float g_wcA[32], g_wcB[32], g_wcC[32];
__device__ float g_bcv[3];
__device__ int   g_args64;

__device__ __forceinline__ float frcp(float x) { float y; asm("rcp.approx.f32 %0, %1;" : "=f"(y) : "f"(x)); return y; }
__device__ __forceinline__ float fex2(float x) { float y; asm("ex2.approx.f32 %0, %1;" : "=f"(y) : "f"(x)); return y; }

// ---------------- packed f32x2 helpers ----------------
__device__ __forceinline__ float2 fma2(float2 a, float2 b, float2 c) {
    float2 r;
    asm("fma.rn.f32x2 %0, %1, %2, %3;"
        : "=l"(*(unsigned long long*)&r)
        : "l"(*(const unsigned long long*)&a),
          "l"(*(const unsigned long long*)&b),
          "l"(*(const unsigned long long*)&c));
    return r;
}
__device__ __forceinline__ float2 mul2(float2 a, float2 b) {
    float2 r;
    asm("mul.rn.f32x2 %0, %1, %2;"
        : "=l"(*(unsigned long long*)&r)
        : "l"(*(const unsigned long long*)&a),
          "l"(*(const unsigned long long*)&b));
    return r;
}
__device__ __forceinline__ float2 add2(float2 a, float2 b) {
    float2 r;
    asm("add.rn.f32x2 %0, %1, %2;"
        : "=l"(*(unsigned long long*)&r)
        : "l"(*(const unsigned long long*)&a),
          "l"(*(const unsigned long long*)&b));
    return r;
}
__device__ __forceinline__ float2 d2(float v) { return make_float2(v, v); }

// packed fast gelu: 0.5*(x + |x|*erf(|x|/sqrt2)), erf via A&S 7.1.25 3-term
__device__ __forceinline__ float2 gelu2(float2 x) {
    unsigned long long ux = (*(unsigned long long*)&x) & 0x7FFFFFFF7FFFFFFFULL;
    float2 ax = *(float2*)&ux;
    float2 z  = mul2(ax, d2(0.70710678118654752f));
    float2 q  = fma2(z, d2(0.47047f), d2(1.0f));
    float2 t; t.x = frcp(q.x); t.y = frcp(q.y);
    float2 s  = mul2(mul2(z, z), d2(-1.4426950408889634f));
    float2 e; e.x = fex2(s.x); e.y = fex2(s.y);
    float2 h  = fma2(d2(0.7478556f), t, d2(-0.0958798f));
    h = fma2(h, t, d2(0.3480242f));
    h = mul2(h, t);
    float2 he = mul2(h, e);
    float2 E  = fma2(he, d2(-1.0f), d2(1.0f));
    float2 g  = mul2(ax, E);
    return mul2(add2(x, g), d2(0.5f));
}

// m16n8k16 fp16 MMA, row.col, fp32 accumulate in-place
__device__ __forceinline__ void mma16(float* d, unsigned a0, unsigned a1, unsigned a2, unsigned a3,
                                      unsigned b0, unsigned b1) {
    asm volatile(
        "mma.sync.aligned.m16n8k16.row.col.f32.f16.f16.f32 "
        "{%0,%1,%2,%3}, {%4,%5,%6,%7}, {%8,%9}, {%0,%1,%2,%3};"
        : "+f"(d[0]), "+f"(d[1]), "+f"(d[2]), "+f"(d[3])
        : "r"(a0), "r"(a1), "r"(a2), "r"(a3), "r"(b0), "r"(b1));
}

// channel -> permuted position within a 32-float P/Q row
__device__ __forceinline__ int permc(int c) {
    return ((c >> 1) & 3) * 8 + ((c >> 3) << 1) + (c & 1);
}

// ---------------- kernel 1: P/Q GEMM (blocks 0..BB*NT-1) + fused prep (last block) --------
__global__ void pq_kernel(
    const float* __restrict__ If,
    const float* __restrict__ W1, const float* __restrict__ g1, const float* __restrict__ b1,
    const float* __restrict__ m1, const float* __restrict__ v1,
    const float* __restrict__ W2, const float* __restrict__ g2, const float* __restrict__ b2,
    const float* __restrict__ m2, const float* __restrict__ v2,
    const float* __restrict__ W3, const float* __restrict__ g3, const float* __restrict__ b3,
    const float* __restrict__ m3, const float* __restrict__ v3,
    const float* __restrict__ W4, const float* __restrict__ g4, const float* __restrict__ b4,
    const float* __restrict__ m4, const float* __restrict__ v4,
    const float* __restrict__ Wc, const float* __restrict__ bc,
    const int*   __restrict__ args_i32)
{
    int tid = threadIdx.x;

    // ---- last block: main-side prep (weights packing, biases, args dtype) ----
    if (blockIdx.x == BB*NT) {
        __shared__ float inv2[32], inv3[32], inv4[32];
        __shared__ int flag;
        if (tid == 0) flag = 0;
        if (tid < 32) {
            float i1 = g1[tid]*rsqrtf(v1[tid]+EPSL);
            g_t1[tid] = b1[tid] - m1[tid]*i1;
            float i2 = g2[tid]*rsqrtf(v2[tid]+EPSL); inv2[tid]=i2; g_t2[tid]=b2[tid]-m2[tid]*i2;
            float i3 = g3[tid]*rsqrtf(v3[tid]+EPSL); inv3[tid]=i3; g_t3[tid]=b3[tid]-m3[tid]*i3;
            float i4 = g4[tid]*rsqrtf(v4[tid]+EPSL); inv4[tid]=i4; g_t4[tid]=b4[tid]-m4[tid]*i4;
            g_wcA[tid]=Wc[tid]; g_wcB[tid]=Wc[32+tid]; g_wcC[tid]=Wc[64+tid];
            g_w1p[tid]=W1[tid*CT+64]*i1; g_w1a[tid]=W1[tid*CT+65]*i1; g_w1b[tid]=W1[tid*CT+66]*i1;
        }
        if (tid < 3) g_bcv[tid] = bc[tid];
        __syncthreads();
        // parallel args-dtype detect: int64 little-endian => odd words all zero
        if (tid < 128) {
            if (args_i32[2*tid+1] != 0) flag = 1;
        }
        __syncthreads();
        if (tid == 0) g_args64 = (flag == 0);
        // packed fp16 weights: idx = k2*32 + n
        for (int idx = tid; idx < 512; idx += blockDim.x) {
            int k2 = idx >> 5, n = idx & 31;
            __half2 p;
            p = __floats2half2_rn(W2[n*32 + 2*k2]*inv2[n], W2[n*32 + 2*k2 + 1]*inv2[n]);
            g_W2p[idx] = *(unsigned*)&p;
            p = __floats2half2_rn(W3[n*32 + 2*k2]*inv3[n], W3[n*32 + 2*k2 + 1]*inv3[n]);
            g_W3p[idx] = *(unsigned*)&p;
            p = __floats2half2_rn(W4[n*32 + 2*k2]*inv4[n], W4[n*32 + 2*k2 + 1]*inv4[n]);
            g_W4p[idx] = *(unsigned*)&p;
        }
        return;
    }

    // ---- P/Q GEMM blocks: fold W1 locally, compute, store permuted ----
    __shared__ float inv1s[32];
    __shared__ float wf[2048];
    __shared__ float tb[256*33];

    int b    = blockIdx.x / NT;
    int tile = blockIdx.x % NT;
    int n0   = tile * 256;

    if (tid < 32) inv1s[tid] = g1[tid]*rsqrtf(v1[tid]+EPSL);
    __syncthreads();
    for (int idx = tid; idx < 2048; idx += 256) {
        int r = idx >> 5, i = idx & 31;
        wf[idx] = (r < 32) ? W1[r*CT + i] * inv1s[r]
                           : W1[(r-32)*CT + 32 + i] * inv1s[r-32];
    }

    int n = n0 + tid;
    float x[32];
    #pragma unroll
    for (int i = 0; i < 32; i++) x[i] = If[((size_t)b*32 + i)*NN + n];
    __syncthreads();

    size_t base = ((size_t)b*NN + n0) * 32;

    #pragma unroll
    for (int c = 0; c < 32; c++) {
        float acc = 0.f;
        #pragma unroll
        for (int i = 0; i < 32; i += 4) {
            float4 w = *(const float4*)&wf[c*32 + i];
            acc += w.x*x[i] + w.y*x[i+1] + w.z*x[i+2] + w.w*x[i+3];
        }
        tb[tid*33 + c] = acc;
    }
    __syncthreads();
    for (int idx = tid; idx < 8192; idx += 256)
        g_P[base + (idx & ~31) + permc(idx & 31)] = tb[(idx >> 5)*33 + (idx & 31)];
    __syncthreads();

    #pragma unroll
    for (int c = 0; c < 32; c++) {
        float acc = 0.f;
        #pragma unroll
        for (int i = 0; i < 32; i += 4) {
            float4 w = *(const float4*)&wf[(32+c)*32 + i];
            acc += w.x*x[i] + w.y*x[i+1] + w.z*x[i+2] + w.w*x[i+3];
        }
        tb[tid*33 + c] = acc;
    }
    __syncthreads();
    for (int idx = tid; idx < 8192; idx += 256)
        g_Q[base + (idx & ~31) + permc(idx & 31)] = tb[(idx >> 5)*33 + (idx & 31)];
}

// ---------------- register-resident MLP layer (single m16 tile per warp) ----------------
// x layout: x[nt*4 + 2*hh + par], channel = 8*nt + 2*tg + par, row = g + 8*hh
template<bool ADD>
__device__ __forceinline__ void layer_reg(
    const float* xin, float* xout,
    const unsigned* __restrict__ wp, const float* __restrict__ bias,
    const float* resid, int g, int tg)
{
    unsigned ah[8];
    #pragma unroll
    for (int nt = 0; nt < 4; nt++) {
        #pragma unroll
        for (int hh = 0; hh < 2; hh++) {
            __half2 p = __floats2half2_rn(xin[nt*4 + 2*hh], xin[nt*4 + 2*hh + 1]);
            ah[nt*2 + hh] = *(unsigned*)&p;
        }
    }
    float d[16];
    #pragma unroll
    for (int nt = 0; nt < 4; nt++) {
        float2 bv = __ldg((const float2*)bias + 4*nt + tg);
        d[nt*4 + 0] = bv.x; d[nt*4 + 1] = bv.y;
        d[nt*4 + 2] = bv.x; d[nt*4 + 3] = bv.y;
    }
    #pragma unroll
    for (int ks = 0; ks < 2; ks++) {
        #pragma unroll
        for (int nt = 0; nt < 4; nt++) {
            unsigned b0 = __ldg(wp + (ks*8 + tg    )*32 + 8*nt + g);
            unsigned b1 = __ldg(wp + (ks*8 + tg + 4)*32 + 8*nt + g);
            mma16(d + nt*4, ah[4*ks], ah[4*ks+1], ah[4*ks+2], ah[4*ks+3], b0, b1);
        }
    }
    #pragma unroll
    for (int i = 0; i < 16; i += 2) {
        float2 v = make_float2(d[i], d[i+1]);
        if (ADD) v = add2(v, make_float2(resid[i], resid[i+1]));
        float2 r = gelu2(v);
        xout[i] = r.x; xout[i+1] = r.y;
    }
}

// ---------------- kernel 2: fused MLP + softmax epilogue ----------------
// block: 8 samples x 16 k. warp w: rows 0-7 = k=2w, rows 8-15 = k=2w+1, sample n0+g.
__global__ void __launch_bounds__(256) main_kernel(
    const float* __restrict__ Pf,
    const float* __restrict__ Of,
    const void*  __restrict__ args,
    float* __restrict__ out)
{
    __shared__ float sU[NUMK][8];
    __shared__ float sOm[NUMK][8];

    int b  = blockIdx.x / NB2;
    int n0 = (blockIdx.x % NB2) * 8;
    int tid = threadIdx.x;
    int w = tid >> 5, lane = tid & 31;
    int g = lane >> 2, tg = lane & 3;

    float xa[16], xb[16];
    float pfs[2];
    int n = n0 + g;

    // stage 1: h1 in D-frag register layout; hh selects k = 2w+hh
    {
        float2 w1p2[4], w1a2[4], w1b2[4], t12[4];
        #pragma unroll
        for (int q = 0; q < 4; q++) {
            w1p2[q] = __ldg((const float2*)g_w1p + 4*q + tg);
            w1a2[q] = __ldg((const float2*)g_w1a + 4*q + tg);
            w1b2[q] = __ldg((const float2*)g_w1b + 4*q + tg);
            t12[q]  = __ldg((const float2*)g_t1  + 4*q + tg);
        }
        int use64 = g_args64;
        const float4* P4 = (const float4*)(g_P + ((size_t)(b*NN + n))*32 + tg*8);
        float4 pA = __ldg(P4), pB = __ldg(P4 + 1);
        float2 pq[4];
        pq[0] = make_float2(pA.x, pA.y); pq[1] = make_float2(pA.z, pA.w);
        pq[2] = make_float2(pB.x, pB.y); pq[3] = make_float2(pB.z, pB.w);
        #pragma unroll
        for (int hh = 0; hh < 2; hh++) {
            int k = 2*w + hh;
            size_t ai = ((size_t)(b*NUMK + k))*NN + n;
            int j;
            if (use64) j = (int)__ldg((const long long*)args + ai);
            else       j = __ldg((const int*)args + ai);
            float pf = __ldg(Pf + (size_t)b*NN + j);
            pfs[hh] = pf;
            float2 pf2 = d2(pf);
            float2 o02 = d2(__ldg(Of + ((size_t)(b*2+0)*NUMK + k)*NN + n));
            float2 o12 = d2(__ldg(Of + ((size_t)(b*2+1)*NUMK + k)*NN + n));
            const float4* Q4 = (const float4*)(g_Q + ((size_t)(b*NN + j))*32 + tg*8);
            float4 qA = __ldg(Q4), qB = __ldg(Q4 + 1);
            float2 qq[4];
            qq[0] = make_float2(qA.x, qA.y); qq[1] = make_float2(qA.z, qA.w);
            qq[2] = make_float2(qB.x, qB.y); qq[3] = make_float2(qB.z, qB.w);
            #pragma unroll
            for (int q = 0; q < 4; q++) {
                float2 z = add2(add2(pq[q], qq[q]), t12[q]);
                z = fma2(w1p2[q], pf2, z);
                z = fma2(w1a2[q], o02, z);
                z = fma2(w1b2[q], o12, z);
                float2 r = gelu2(z);
                xa[q*4 + 2*hh]     = r.x;
                xa[q*4 + 2*hh + 1] = r.y;
            }
        }
    }

    layer_reg<false>(xa, xb, g_W2p, g_t2, nullptr, g, tg);   // h2 = xb
    layer_reg<false>(xb, xa, g_W3p, g_t3, nullptr, g, tg);   // l3 = xa
    layer_reg<true >(xa, xa, g_W4p, g_t4, xb,      g, tg);   // XF = gelu(h2 + bn4(W4 l3))

    // head: 3x32 dot per (k, n), reduce across tg-lanes, deposit U/Om in smem
    {
        float2 wA2[4], wB2[4], wC2[4];
        #pragma unroll
        for (int nt = 0; nt < 4; nt++) {
            wA2[nt] = __ldg((const float2*)g_wcA + 4*nt + tg);
            wB2[nt] = __ldg((const float2*)g_wcB + 4*nt + tg);
            wC2[nt] = __ldg((const float2*)g_wcC + 4*nt + tg);
        }
        float bc0 = g_bcv[0], bc1 = g_bcv[1], bc2 = g_bcv[2];
        #pragma unroll
        for (int hh = 0; hh < 2; hh++) {
            float2 a2 = d2(0.f), be2 = d2(0.f), om2 = d2(0.f);
            #pragma unroll
            for (int nt = 0; nt < 4; nt++) {
                float2 xp = make_float2(xa[nt*4 + 2*hh], xa[nt*4 + 2*hh + 1]);
                a2  = fma2(wA2[nt], xp, a2);
                be2 = fma2(wB2[nt], xp, be2);
                om2 = fma2(wC2[nt], xp, om2);
            }
            float a = a2.x + a2.y, be = be2.x + be2.y, om = om2.x + om2.y;
            a  += __shfl_xor_sync(0xffffffffu, a, 1);
            a  += __shfl_xor_sync(0xffffffffu, a, 2);
            be += __shfl_xor_sync(0xffffffffu, be, 1);
            be += __shfl_xor_sync(0xffffffffu, be, 2);
            om += __shfl_xor_sync(0xffffffffu, om, 1);
            om += __shfl_xor_sync(0xffffffffu, om, 2);
            if (tg == 0) {
                int k = 2*w + hh;
                sU[k][g]  = (a + bc0 + 1.0f)*pfs[hh] + (be + bc1);
                sOm[k][g] = om + bc2;
            }
        }
    }
    __syncthreads();

    // softmax over k + weighted sum; threads 0-7 each own one sample
    if (tid < 8) {
        float om[NUMK];
        float m = -3.4e38f;
        #pragma unroll
        for (int k = 0; k < NUMK; k++) {
            om[k] = sOm[k][tid];
            m = fmaxf(m, om[k]);
        }
        float num = 0.f, den = 0.f;
        #pragma unroll
        for (int k = 0; k < NUMK; k++) {
            float e = fex2((om[k] - m) * 1.4426950408889634f);
            den += e;
            num += e * sU[k][tid];
        }
        out[(size_t)b*NN + n0 + tid] = num * frcp(den);
    }
}

// ---------------- launch ----------------
extern "C" void kernel_launch(void* const* d_in, const int* in_sizes, int n_in,
                              void* d_out, int out_size)
{
    const float* If = (const float*)d_in[0];
    const float* Pf = (const float*)d_in[1];
    const float* Of = (const float*)d_in[2];
    const void*  args = d_in[3];
    const float* W1 = (const float*)d_in[4];
    const float* g1 = (const float*)d_in[5];
    const float* b1 = (const float*)d_in[6];
    const float* m1 = (const float*)d_in[7];
    const float* v1 = (const float*)d_in[8];
    const float* W2 = (const float*)d_in[9];
    const float* g2 = (const float*)d_in[10];
    const float* b2 = (const float*)d_in[11];
    const float* m2 = (const float*)d_in[12];
    const float* v2 = (const float*)d_in[13];
    const float* W3 = (const float*)d_in[14];
    const float* g3 = (const float*)d_in[15];
    const float* b3 = (const float*)d_in[16];
    const float* m3 = (const float*)d_in[17];
    const float* v3 = (const float*)d_in[18];
    const float* W4 = (const float*)d_in[19];
    const float* g4 = (const float*)d_in[20];
    const float* b4 = (const float*)d_in[21];
    const float* m4 = (const float*)d_in[22];
    const float* v4 = (const float*)d_in[23];
    const float* Wc = (const float*)d_in[24];
    const float* bc = (const float*)d_in[25];

    pq_kernel<<<BB*NT + 1, 256>>>(If,
                                  W1, g1, b1, m1, v1,
                                  W2, g2, b2, m2, v2,
                                  W3, g3, b3, m3, v3,
                                  W4, g4, b4, m4, v4,
                                  Wc, bc, (const int*)args);

    main_kernel<<<BB*NB2, 256>>>(Pf, Of, args, (float*)d_out);
}

// round 16
// speedup vs baseline: 1.1316x; 1.0315x over previous
#include <cuda_runtime.h>
#include <cuda_fp16.h>
#include <cstdint>

#define BB   2
#define CFI  32
#define HH   192
#define WWD  192
#define NN   (HH*WWD)        // 36864
#define NUMK 16
#define CT   67
#define EPSL 1e-5f
#define NT   (NN/256)        // 144 (pq tiles)
#define NB2  (NN/8)          // 4608 main tiles: 8 samples x 16 k per block

// ---------------- scratch (static device globals; no allocation) ----------------
// g_P/g_Q rows are PERMUTED: within a row, channel c sits at
// p = ((c>>1)&3)*8 + ((c>>3)<<1) + (c&1)  (thread tg owns floats [tg*8, tg*8+8))
__device__ float g_P[BB*NN*CFI];
__device__ float g_Q[BB*NN*CFI];

__device__ float g_w1p[32], g_w1a[32], g_w1b[32], g_t1[32];
// packed f16x2 weights per layer: [k2][32] uint32 (single precision pass)
__device__ unsigned g_W2p[512];
__device__ unsigned g_W3p[512];
__device__ unsigned g_W4p[512];
// packed f16x2 head weights: [k2][8] (cols 0=A,1=B,2=Om, 3..7 zero)
__device__ unsigned g_Wcp[128];
__device__ float g_t2[32], g_t3[32], g_t4[32];
__device__ float g_bcv[3];
__device__ int   g_args64;

__device__ __forceinline__ float frcp(float x) { float y; asm("rcp.approx.f32 %0, %1;" : "=f"(y) : "f"(x)); return y; }
__device__ __forceinline__ float fex2(float x) { float y; asm("ex2.approx.f32 %0, %1;" : "=f"(y) : "f"(x)); return y; }

// ---------------- packed f32x2 helpers ----------------
__device__ __forceinline__ float2 fma2(float2 a, float2 b, float2 c) {
    float2 r;
    asm("fma.rn.f32x2 %0, %1, %2, %3;"
        : "=l"(*(unsigned long long*)&r)
        : "l"(*(const unsigned long long*)&a),
          "l"(*(const unsigned long long*)&b),
          "l"(*(const unsigned long long*)&c));
    return r;
}
__device__ __forceinline__ float2 mul2(float2 a, float2 b) {
    float2 r;
    asm("mul.rn.f32x2 %0, %1, %2;"
        : "=l"(*(unsigned long long*)&r)
        : "l"(*(const unsigned long long*)&a),
          "l"(*(const unsigned long long*)&b));
    return r;
}
__device__ __forceinline__ float2 add2(float2 a, float2 b) {
    float2 r;
    asm("add.rn.f32x2 %0, %1, %2;"
        : "=l"(*(unsigned long long*)&r)
        : "l"(*(const unsigned long long*)&a),
          "l"(*(const unsigned long long*)&b));
    return r;
}
__device__ __forceinline__ float2 d2(float v) { return make_float2(v, v); }

// packed fast gelu: 0.5*(x + |x|*erf(|x|/sqrt2)), erf via A&S 7.1.25 3-term
__device__ __forceinline__ float2 gelu2(float2 x) {
    unsigned long long ux = (*(unsigned long long*)&x) & 0x7FFFFFFF7FFFFFFFULL;
    float2 ax = *(float2*)&ux;
    float2 z  = mul2(ax, d2(0.70710678118654752f));
    float2 q  = fma2(z, d2(0.47047f), d2(1.0f));
    float2 t; t.x = frcp(q.x); t.y = frcp(q.y);
    float2 s  = mul2(mul2(z, z), d2(-1.4426950408889634f));
    float2 e; e.x = fex2(s.x); e.y = fex2(s.y);
    float2 h  = fma2(d2(0.7478556f), t, d2(-0.0958798f));
    h = fma2(h, t, d2(0.3480242f));
    h = mul2(h, t);
    float2 he = mul2(h, e);
    float2 E  = fma2(he, d2(-1.0f), d2(1.0f));
    float2 g  = mul2(ax, E);
    return mul2(add2(x, g), d2(0.5f));
}

// m16n8k16 fp16 MMA, row.col, fp32 accumulate in-place
__device__ __forceinline__ void mma16(float* d, unsigned a0, unsigned a1, unsigned a2, unsigned a3,
                                      unsigned b0, unsigned b1) {
    asm volatile(
        "mma.sync.aligned.m16n8k16.row.col.f32.f16.f16.f32 "
        "{%0,%1,%2,%3}, {%4,%5,%6,%7}, {%8,%9}, {%0,%1,%2,%3};"
        : "+f"(d[0]), "+f"(d[1]), "+f"(d[2]), "+f"(d[3])
        : "r"(a0), "r"(a1), "r"(a2), "r"(a3), "r"(b0), "r"(b1));
}

// channel -> permuted position within a 32-float P/Q row
__device__ __forceinline__ int permc(int c) {
    return ((c >> 1) & 3) * 8 + ((c >> 3) << 1) + (c & 1);
}

// ---------------- kernel 1: P/Q GEMM (blocks 0..BB*NT-1) + fused prep (last block) --------
__global__ void pq_kernel(
    const float* __restrict__ If,
    const float* __restrict__ W1, const float* __restrict__ g1, const float* __restrict__ b1,
    const float* __restrict__ m1, const float* __restrict__ v1,
    const float* __restrict__ W2, const float* __restrict__ g2, const float* __restrict__ b2,
    const float* __restrict__ m2, const float* __restrict__ v2,
    const float* __restrict__ W3, const float* __restrict__ g3, const float* __restrict__ b3,
    const float* __restrict__ m3, const float* __restrict__ v3,
    const float* __restrict__ W4, const float* __restrict__ g4, const float* __restrict__ b4,
    const float* __restrict__ m4, const float* __restrict__ v4,
    const float* __restrict__ Wc, const float* __restrict__ bc,
    const int*   __restrict__ args_i32)
{
    int tid = threadIdx.x;

    // ---- last block: main-side prep (weights packing, biases, args dtype) ----
    if (blockIdx.x == BB*NT) {
        __shared__ float inv2[32], inv3[32], inv4[32];
        __shared__ int flag;
        if (tid == 0) flag = 0;
        if (tid < 32) {
            float i1 = g1[tid]*rsqrtf(v1[tid]+EPSL);
            g_t1[tid] = b1[tid] - m1[tid]*i1;
            float i2 = g2[tid]*rsqrtf(v2[tid]+EPSL); inv2[tid]=i2; g_t2[tid]=b2[tid]-m2[tid]*i2;
            float i3 = g3[tid]*rsqrtf(v3[tid]+EPSL); inv3[tid]=i3; g_t3[tid]=b3[tid]-m3[tid]*i3;
            float i4 = g4[tid]*rsqrtf(v4[tid]+EPSL); inv4[tid]=i4; g_t4[tid]=b4[tid]-m4[tid]*i4;
            g_w1p[tid]=W1[tid*CT+64]*i1; g_w1a[tid]=W1[tid*CT+65]*i1; g_w1b[tid]=W1[tid*CT+66]*i1;
        }
        if (tid < 3) g_bcv[tid] = bc[tid];
        __syncthreads();
        // parallel args-dtype detect: int64 little-endian => odd words all zero
        if (tid < 128) {
            if (args_i32[2*tid+1] != 0) flag = 1;
        }
        // head weights packed fp16: [k2][8], rows 0..2 = Wc, rest zero
        if (tid < 128) {
            int k2 = tid >> 3, n = tid & 7;
            float w0 = (n < 3) ? Wc[n*32 + 2*k2]     : 0.f;
            float w1 = (n < 3) ? Wc[n*32 + 2*k2 + 1] : 0.f;
            __half2 p = __floats2half2_rn(w0, w1);
            g_Wcp[tid] = *(unsigned*)&p;
        }
        __syncthreads();
        if (tid == 0) g_args64 = (flag == 0);
        // packed fp16 layer weights: idx = k2*32 + n
        for (int idx = tid; idx < 512; idx += blockDim.x) {
            int k2 = idx >> 5, n = idx & 31;
            __half2 p;
            p = __floats2half2_rn(W2[n*32 + 2*k2]*inv2[n], W2[n*32 + 2*k2 + 1]*inv2[n]);
            g_W2p[idx] = *(unsigned*)&p;
            p = __floats2half2_rn(W3[n*32 + 2*k2]*inv3[n], W3[n*32 + 2*k2 + 1]*inv3[n]);
            g_W3p[idx] = *(unsigned*)&p;
            p = __floats2half2_rn(W4[n*32 + 2*k2]*inv4[n], W4[n*32 + 2*k2 + 1]*inv4[n]);
            g_W4p[idx] = *(unsigned*)&p;
        }
        return;
    }

    // ---- P/Q GEMM blocks: fold W1 locally, compute, store permuted ----
    __shared__ float inv1s[32];
    __shared__ float wf[2048];
    __shared__ float tb[256*33];

    int b    = blockIdx.x / NT;
    int tile = blockIdx.x % NT;
    int n0   = tile * 256;

    if (tid < 32) inv1s[tid] = g1[tid]*rsqrtf(v1[tid]+EPSL);
    __syncthreads();
    for (int idx = tid; idx < 2048; idx += 256) {
        int r = idx >> 5, i = idx & 31;
        wf[idx] = (r < 32) ? W1[r*CT + i] * inv1s[r]
                           : W1[(r-32)*CT + 32 + i] * inv1s[r-32];
    }

    int n = n0 + tid;
    float x[32];
    #pragma unroll
    for (int i = 0; i < 32; i++) x[i] = If[((size_t)b*32 + i)*NN + n];
    __syncthreads();

    size_t base = ((size_t)b*NN + n0) * 32;

    #pragma unroll
    for (int c = 0; c < 32; c++) {
        float acc = 0.f;
        #pragma unroll
        for (int i = 0; i < 32; i += 4) {
            float4 w = *(const float4*)&wf[c*32 + i];
            acc += w.x*x[i] + w.y*x[i+1] + w.z*x[i+2] + w.w*x[i+3];
        }
        tb[tid*33 + c] = acc;
    }
    __syncthreads();
    for (int idx = tid; idx < 8192; idx += 256)
        g_P[base + (idx & ~31) + permc(idx & 31)] = tb[(idx >> 5)*33 + (idx & 31)];
    __syncthreads();

    #pragma unroll
    for (int c = 0; c < 32; c++) {
        float acc = 0.f;
        #pragma unroll
        for (int i = 0; i < 32; i += 4) {
            float4 w = *(const float4*)&wf[(32+c)*32 + i];
            acc += w.x*x[i] + w.y*x[i+1] + w.z*x[i+2] + w.w*x[i+3];
        }
        tb[tid*33 + c] = acc;
    }
    __syncthreads();
    for (int idx = tid; idx < 8192; idx += 256)
        g_Q[base + (idx & ~31) + permc(idx & 31)] = tb[(idx >> 5)*33 + (idx & 31)];
}

// ---------------- register-resident MLP layer (single m16 tile per warp) ----------------
// x layout: x[nt*4 + 2*hh + par], channel = 8*nt + 2*tg + par, row = g + 8*hh
template<bool ADD>
__device__ __forceinline__ void layer_reg(
    const float* xin, float* xout,
    const unsigned* __restrict__ wp, const float* __restrict__ bias,
    const float* resid, int g, int tg)
{
    unsigned ah[8];
    #pragma unroll
    for (int nt = 0; nt < 4; nt++) {
        #pragma unroll
        for (int hh = 0; hh < 2; hh++) {
            __half2 p = __floats2half2_rn(xin[nt*4 + 2*hh], xin[nt*4 + 2*hh + 1]);
            ah[nt*2 + hh] = *(unsigned*)&p;
        }
    }
    float d[16];
    #pragma unroll
    for (int nt = 0; nt < 4; nt++) {
        float2 bv = __ldg((const float2*)bias + 4*nt + tg);
        d[nt*4 + 0] = bv.x; d[nt*4 + 1] = bv.y;
        d[nt*4 + 2] = bv.x; d[nt*4 + 3] = bv.y;
    }
    #pragma unroll
    for (int ks = 0; ks < 2; ks++) {
        #pragma unroll
        for (int nt = 0; nt < 4; nt++) {
            unsigned b0 = __ldg(wp + (ks*8 + tg    )*32 + 8*nt + g);
            unsigned b1 = __ldg(wp + (ks*8 + tg + 4)*32 + 8*nt + g);
            mma16(d + nt*4, ah[4*ks], ah[4*ks+1], ah[4*ks+2], ah[4*ks+3], b0, b1);
        }
    }
    #pragma unroll
    for (int i = 0; i < 16; i += 2) {
        float2 v = make_float2(d[i], d[i+1]);
        if (ADD) v = add2(v, make_float2(resid[i], resid[i+1]));
        float2 r = gelu2(v);
        xout[i] = r.x; xout[i+1] = r.y;
    }
}

// ---------------- kernel 2: fused MLP + mma head + softmax epilogue ----------------
// block: 8 samples x 16 k. warp w: rows 0-7 = k=2w, rows 8-15 = k=2w+1, sample n0+g.
__global__ void __launch_bounds__(256) main_kernel(
    const float* __restrict__ Pf,
    const float* __restrict__ Of,
    const void*  __restrict__ args,
    float* __restrict__ out)
{
    __shared__ float sU[NUMK][8];
    __shared__ float sOm[NUMK][8];

    int b  = blockIdx.x / NB2;
    int n0 = (blockIdx.x % NB2) * 8;
    int tid = threadIdx.x;
    int w = tid >> 5, lane = tid & 31;
    int g = lane >> 2, tg = lane & 3;

    float xa[16], xb[16];
    float pfs[2];
    int n = n0 + g;

    // stage 1: h1 in D-frag register layout; hh selects k = 2w+hh
    {
        float2 w1p2[4], w1a2[4], w1b2[4], t12[4];
        #pragma unroll
        for (int q = 0; q < 4; q++) {
            w1p2[q] = __ldg((const float2*)g_w1p + 4*q + tg);
            w1a2[q] = __ldg((const float2*)g_w1a + 4*q + tg);
            w1b2[q] = __ldg((const float2*)g_w1b + 4*q + tg);
            t12[q]  = __ldg((const float2*)g_t1  + 4*q + tg);
        }
        int use64 = g_args64;
        const float4* P4 = (const float4*)(g_P + ((size_t)(b*NN + n))*32 + tg*8);
        float4 pA = __ldg(P4), pB = __ldg(P4 + 1);
        float2 pq[4];
        pq[0] = make_float2(pA.x, pA.y); pq[1] = make_float2(pA.z, pA.w);
        pq[2] = make_float2(pB.x, pB.y); pq[3] = make_float2(pB.z, pB.w);
        #pragma unroll
        for (int hh = 0; hh < 2; hh++) {
            int k = 2*w + hh;
            size_t ai = ((size_t)(b*NUMK + k))*NN + n;
            int j;
            if (use64) j = (int)__ldg((const long long*)args + ai);
            else       j = __ldg((const int*)args + ai);
            float pf = __ldg(Pf + (size_t)b*NN + j);
            pfs[hh] = pf;
            float2 pf2 = d2(pf);
            float2 o02 = d2(__ldg(Of + ((size_t)(b*2+0)*NUMK + k)*NN + n));
            float2 o12 = d2(__ldg(Of + ((size_t)(b*2+1)*NUMK + k)*NN + n));
            const float4* Q4 = (const float4*)(g_Q + ((size_t)(b*NN + j))*32 + tg*8);
            float4 qA = __ldg(Q4), qB = __ldg(Q4 + 1);
            float2 qq[4];
            qq[0] = make_float2(qA.x, qA.y); qq[1] = make_float2(qA.z, qA.w);
            qq[2] = make_float2(qB.x, qB.y); qq[3] = make_float2(qB.z, qB.w);
            #pragma unroll
            for (int q = 0; q < 4; q++) {
                float2 z = add2(add2(pq[q], qq[q]), t12[q]);
                z = fma2(w1p2[q], pf2, z);
                z = fma2(w1a2[q], o02, z);
                z = fma2(w1b2[q], o12, z);
                float2 r = gelu2(z);
                xa[q*4 + 2*hh]     = r.x;
                xa[q*4 + 2*hh + 1] = r.y;
            }
        }
    }

    layer_reg<false>(xa, xb, g_W2p, g_t2, nullptr, g, tg);   // h2 = xb
    layer_reg<false>(xb, xa, g_W3p, g_t3, nullptr, g, tg);   // l3 = xa
    layer_reg<true >(xa, xa, g_W4p, g_t4, xb,      g, tg);   // XF = gelu(h2 + bn4(W4 l3))

    // head as one fp16 mma: D cols 0=A, 1=B, 2=Om; rows = instances
    {
        unsigned ah[8];
        #pragma unroll
        for (int nt = 0; nt < 4; nt++) {
            #pragma unroll
            for (int hh = 0; hh < 2; hh++) {
                __half2 p = __floats2half2_rn(xa[nt*4 + 2*hh], xa[nt*4 + 2*hh + 1]);
                ah[nt*2 + hh] = *(unsigned*)&p;
            }
        }
        float dh[4] = {0.f, 0.f, 0.f, 0.f};
        #pragma unroll
        for (int ks = 0; ks < 2; ks++) {
            unsigned b0 = __ldg(g_Wcp + (ks*8 + tg    )*8 + g);
            unsigned b1 = __ldg(g_Wcp + (ks*8 + tg + 4)*8 + g);
            mma16(dh, ah[4*ks], ah[4*ks+1], ah[4*ks+2], ah[4*ks+3], b0, b1);
        }
        float bc0 = g_bcv[0], bc1 = g_bcv[1], bc2 = g_bcv[2];
        if (tg == 0) {
            #pragma unroll
            for (int hh = 0; hh < 2; hh++) {
                int k = 2*w + hh;
                sU[k][g] = (dh[2*hh] + bc0 + 1.0f)*pfs[hh] + (dh[2*hh+1] + bc1);
            }
        }
        if (tg == 1) {
            #pragma unroll
            for (int hh = 0; hh < 2; hh++) {
                int k = 2*w + hh;
                sOm[k][g] = dh[2*hh] + bc2;
            }
        }
    }
    __syncthreads();

    // softmax over k + weighted sum; threads 0-7 each own one sample
    if (tid < 8) {
        float om[NUMK];
        float m = -3.4e38f;
        #pragma unroll
        for (int k = 0; k < NUMK; k++) {
            om[k] = sOm[k][tid];
            m = fmaxf(m, om[k]);
        }
        float num = 0.f, den = 0.f;
        #pragma unroll
        for (int k = 0; k < NUMK; k++) {
            float e = fex2((om[k] - m) * 1.4426950408889634f);
            den += e;
            num += e * sU[k][tid];
        }
        out[(size_t)b*NN + n0 + tid] = num * frcp(den);
    }
}

// ---------------- launch ----------------
extern "C" void kernel_launch(void* const* d_in, const int* in_sizes, int n_in,
                              void* d_out, int out_size)
{
    const float* If = (const float*)d_in[0];
    const float* Pf = (const float*)d_in[1];
    const float* Of = (const float*)d_in[2];
    const void*  args = d_in[3];
    const float* W1 = (const float*)d_in[4];
    const float* g1 = (const float*)d_in[5];
    const float* b1 = (const float*)d_in[6];
    const float* m1 = (const float*)d_in[7];
    const float* v1 = (const float*)d_in[8];
    const float* W2 = (const float*)d_in[9];
    const float* g2 = (const float*)d_in[10];
    const float* b2 = (const float*)d_in[11];
    const float* m2 = (const float*)d_in[12];
    const float* v2 = (const float*)d_in[13];
    const float* W3 = (const float*)d_in[14];
    const float* g3 = (const float*)d_in[15];
    const float* b3 = (const float*)d_in[16];
    const float* m3 = (const float*)d_in[17];
    const float* v3 = (const float*)d_in[18];
    const float* W4 = (const float*)d_in[19];
    const float* g4 = (const float*)d_in[20];
    const float* b4 = (const float*)d_in[21];
    const float* m4 = (const float*)d_in[22];
    const float* v4 = (const float*)d_in[23];
    const float* Wc = (const float*)d_in[24];
    const float* bc = (const float*)d_in[25];

    pq_kernel<<<BB*NT + 1, 256>>>(If,
                                  W1, g1, b1, m1, v1,
                                  W2, g2, b2, m2, v2,
                                  W3, g3, b3, m3, v3,
                                  W4, g4, b4, m4, v4,
                                  Wc, bc, (const int*)args);

    main_kernel<<<BB*NB2, 256>>>(Pf, Of, args, (float*)d_out);
}